// round 3
// baseline (speedup 1.0000x reference)
#include <cuda_runtime.h>
#include <math.h>

#define NN   3072
#define EE   98304
#define FDIM 1024
#define HD   64

// ---------------- scratch (static device arrays; no allocation) ----------------
__device__ int           g_cell[NN * NN];       // packed (edge_id<<3)|etype, 0 = no edge
__device__ unsigned char g_mask[NN * NN];       // 0 = -inf, 1..4 = etype
__device__ float g_q [NN * FDIM];
__device__ float g_k [NN * FDIM];
__device__ float g_v [NN * FDIM];
__device__ float g_q2[NN * FDIM];
__device__ float g_k2[NN * FDIM];
__device__ float g_v2[NN * FDIM];
__device__ float g_att[NN * FDIM];

// ---------------- mask construction ----------------
__global__ void zero_cells_kernel() {
    int i = blockIdx.x * blockDim.x + threadIdx.x;     // over NN*NN/4 int4
    if (i < NN * NN / 4) {
        ((int4*)g_cell)[i] = make_int4(0, 0, 0, 0);
    }
}

__global__ void scatter_kernel(const int* __restrict__ ei, const int* __restrict__ et) {
    int e = blockIdx.x * blockDim.x + threadIdx.x;
    if (e < EE) {
        int s = ei[e];
        int d = ei[EE + e];
        int val = (e << 3) | et[e];                    // etype in 1..4 (3 bits); max e = last-wins
        atomicMax(&g_cell[s * NN + d], val);
    }
}

__global__ void build_mask_kernel() {
    int i = blockIdx.x * blockDim.x + threadIdx.x;
    int i4 = i * 4;
    if (i4 < NN * NN) {
        int row  = i4 / NN;
        int colb = i4 - row * NN;                      // NN % 4 == 0: all 4 in same row
        int4 c = *(const int4*)(g_cell + i4);
        uchar4 m;
        m.x = c.x ? (unsigned char)(c.x & 7) : (unsigned char)((row == colb + 0) ? 4 : 0);
        m.y = c.y ? (unsigned char)(c.y & 7) : (unsigned char)((row == colb + 1) ? 4 : 0);
        m.z = c.z ? (unsigned char)(c.z & 7) : (unsigned char)((row == colb + 2) ? 4 : 0);
        m.w = c.w ? (unsigned char)(c.w & 7) : (unsigned char)((row == colb + 3) ? 4 : 0);
        *(uchar4*)(g_mask + i4) = m;
    }
}

// ---------------- fp32 GEMM: Y[M,N] = X[M,K] @ W[N,K]^T + bias ----------------
// Fixed M=3072, N=1024, K=1024. Tile 128x128xBK16, 256 threads, 8x8/thread.
__global__ __launch_bounds__(256) void gemm_bias_kernel(
    const float* __restrict__ X, const float* __restrict__ W,
    const float* __restrict__ bias, float* __restrict__ Y)
{
    const int K = 1024, NC = 1024;
    __shared__ float As[16][132];   // padded to reduce transpose-store conflicts
    __shared__ float Bs[16][132];

    const int tid  = threadIdx.x;
    const int tx   = tid & 15;
    const int ty   = tid >> 4;
    const int row0 = blockIdx.y << 7;
    const int col0 = blockIdx.x << 7;
    const int lr   = tid >> 2;          // 0..63
    const int lc   = (tid & 3) << 2;    // 0,4,8,12

    const float* Xp = X + (size_t)(row0 + lr) * K + lc;
    const float* Wp = W + (size_t)(col0 + lr) * K + lc;

    float acc[8][8];
    #pragma unroll
    for (int i = 0; i < 8; i++)
        #pragma unroll
        for (int j = 0; j < 8; j++) acc[i][j] = 0.f;

    for (int k0 = 0; k0 < K; k0 += 16) {
        float4 xa = *(const float4*)(Xp + k0);
        float4 xb = *(const float4*)(Xp + (size_t)64 * K + k0);
        float4 wa = *(const float4*)(Wp + k0);
        float4 wb = *(const float4*)(Wp + (size_t)64 * K + k0);
        As[lc+0][lr]    = xa.x; As[lc+1][lr]    = xa.y; As[lc+2][lr]    = xa.z; As[lc+3][lr]    = xa.w;
        As[lc+0][lr+64] = xb.x; As[lc+1][lr+64] = xb.y; As[lc+2][lr+64] = xb.z; As[lc+3][lr+64] = xb.w;
        Bs[lc+0][lr]    = wa.x; Bs[lc+1][lr]    = wa.y; Bs[lc+2][lr]    = wa.z; Bs[lc+3][lr]    = wa.w;
        Bs[lc+0][lr+64] = wb.x; Bs[lc+1][lr+64] = wb.y; Bs[lc+2][lr+64] = wb.z; Bs[lc+3][lr+64] = wb.w;
        __syncthreads();

        #pragma unroll
        for (int kk = 0; kk < 16; kk++) {
            float a[8], b[8];
            *(float4*)(a)     = *(const float4*)&As[kk][ty * 8];
            *(float4*)(a + 4) = *(const float4*)&As[kk][ty * 8 + 4];
            *(float4*)(b)     = *(const float4*)&Bs[kk][tx * 8];
            *(float4*)(b + 4) = *(const float4*)&Bs[kk][tx * 8 + 4];
            #pragma unroll
            for (int i = 0; i < 8; i++)
                #pragma unroll
                for (int j = 0; j < 8; j++)
                    acc[i][j] = fmaf(a[i], b[j], acc[i][j]);
        }
        __syncthreads();
    }

    float bv[8];
    *(float4*)(bv)     = *(const float4*)&bias[col0 + tx * 8];
    *(float4*)(bv + 4) = *(const float4*)&bias[col0 + tx * 8 + 4];
    #pragma unroll
    for (int i = 0; i < 8; i++) {
        float* yp = Y + (size_t)(row0 + ty * 8 + i) * NC + col0 + tx * 8;
        float4 o1 = make_float4(acc[i][0] + bv[0], acc[i][1] + bv[1],
                                acc[i][2] + bv[2], acc[i][3] + bv[3]);
        float4 o2 = make_float4(acc[i][4] + bv[4], acc[i][5] + bv[5],
                                acc[i][6] + bv[6], acc[i][7] + bv[7]);
        *(float4*)yp       = o1;
        *(float4*)(yp + 4) = o2;
    }
}

// ---------------- flash attention with edge mask ----------------
// Grid: (48 query tiles, 16 heads). Block: 256 threads (16x16), 4x4 frag.
// Dynamic smem: Qs/Ks/Vs/Ps [64][65] + wtab + mask tile bytes.
#define ATTN_SMEM_BYTES 70688

__global__ __launch_bounds__(256) void attn_kernel(const float* __restrict__ etw)
{
    extern __shared__ float sm[];
    float* Qs  = sm;                 // [64][65]  (row r, dim d)
    float* Ks  = sm + 4160;          // [64][65]  (key c, dim d)
    float* Vs  = sm + 8320;          // [64][65]  (key j, dim d)
    float* Ps  = sm + 12480;         // [64][65]  TRANSPOSED: (key j, query r)
    float* wsh = sm + 16640;         // wsh[1..4] = softplus(etw[0..3])
    unsigned char* smc = (unsigned char*)(sm + 16648);  // 64x64 mask codes

    const int tid = threadIdx.x;
    const int tx4 = (tid & 15) << 2;
    const int ty4 = (tid >> 4) << 2;
    const int q0  = blockIdx.x * 64;
    const int h   = blockIdx.y;

    if (tid < 4) wsh[1 + tid] = log1pf(expf(etw[tid]));  // softplus

    const int lr  = tid >> 4;           // 0..15
    const int ld4 = (tid & 15) << 2;    // 0..60

    // Q tile (once)
    {
        const float* qp = g_q2 + (size_t)(q0 + lr) * FDIM + h * HD + ld4;
        #pragma unroll
        for (int i = 0; i < 4; i++) {
            float4 t = *(const float4*)(qp + (size_t)i * 16 * FDIM);
            float* d = &Qs[(lr + i * 16) * 65 + ld4];
            d[0] = t.x; d[1] = t.y; d[2] = t.z; d[3] = t.w;
        }
    }

    float o[4][4];
    #pragma unroll
    for (int i = 0; i < 4; i++) { o[i][0] = o[i][1] = o[i][2] = o[i][3] = 0.f; }
    float mS[4] = {-1e30f, -1e30f, -1e30f, -1e30f};
    float lS[4] = {0.f, 0.f, 0.f, 0.f};

    __syncthreads();   // Qs + wsh ready; also guards first K/V load

    const int mr = tid >> 2;
    const int mo = (tid & 3) << 4;

    for (int t = 0; t < NN / 64; t++) {
        const int k0 = t * 64;
        // ---- load K, V, mask tile ----
        const float* kp = g_k2 + (size_t)(k0 + lr) * FDIM + h * HD + ld4;
        const float* vp = g_v2 + (size_t)(k0 + lr) * FDIM + h * HD + ld4;
        #pragma unroll
        for (int i = 0; i < 4; i++) {
            float4 tk = *(const float4*)(kp + (size_t)i * 16 * FDIM);
            float4 tv = *(const float4*)(vp + (size_t)i * 16 * FDIM);
            float* dk = &Ks[(lr + i * 16) * 65 + ld4];
            dk[0] = tk.x; dk[1] = tk.y; dk[2] = tk.z; dk[3] = tk.w;
            float* dv = &Vs[(lr + i * 16) * 65 + ld4];
            dv[0] = tv.x; dv[1] = tv.y; dv[2] = tv.z; dv[3] = tv.w;
        }
        *(uint4*)(smc + mr * 64 + mo) =
            *(const uint4*)(g_mask + (size_t)(q0 + mr) * NN + k0 + mo);
        __syncthreads();

        // ---- S = Q K^T (4x4 frag, inner over d) ----
        float s[4][4];
        #pragma unroll
        for (int i = 0; i < 4; i++) { s[i][0] = s[i][1] = s[i][2] = s[i][3] = 0.f; }
        #pragma unroll 4
        for (int d = 0; d < 64; d++) {
            float a0 = Qs[(ty4 + 0) * 65 + d];
            float a1 = Qs[(ty4 + 1) * 65 + d];
            float a2 = Qs[(ty4 + 2) * 65 + d];
            float a3 = Qs[(ty4 + 3) * 65 + d];
            float b0 = Ks[(tx4 + 0) * 65 + d];
            float b1 = Ks[(tx4 + 1) * 65 + d];
            float b2 = Ks[(tx4 + 2) * 65 + d];
            float b3 = Ks[(tx4 + 3) * 65 + d];
            s[0][0] = fmaf(a0, b0, s[0][0]); s[0][1] = fmaf(a0, b1, s[0][1]);
            s[0][2] = fmaf(a0, b2, s[0][2]); s[0][3] = fmaf(a0, b3, s[0][3]);
            s[1][0] = fmaf(a1, b0, s[1][0]); s[1][1] = fmaf(a1, b1, s[1][1]);
            s[1][2] = fmaf(a1, b2, s[1][2]); s[1][3] = fmaf(a1, b3, s[1][3]);
            s[2][0] = fmaf(a2, b0, s[2][0]); s[2][1] = fmaf(a2, b1, s[2][1]);
            s[2][2] = fmaf(a2, b2, s[2][2]); s[2][3] = fmaf(a2, b3, s[2][3]);
            s[3][0] = fmaf(a3, b0, s[3][0]); s[3][1] = fmaf(a3, b1, s[3][1]);
            s[3][2] = fmaf(a3, b2, s[3][2]); s[3][3] = fmaf(a3, b3, s[3][3]);
        }

        // ---- masked online softmax (row groups = 16 lanes, width-16 shuffles) ----
        #pragma unroll
        for (int rr = 0; rr < 4; rr++) {
            float vals[4];
            float mx = -1e30f;
            #pragma unroll
            for (int cc = 0; cc < 4; cc++) {
                int code = smc[(ty4 + rr) * 64 + tx4 + cc];
                float vv = code ? fmaf(s[rr][cc], 0.125f, wsh[code]) : -1e30f;
                vals[cc] = vv;
                mx = fmaxf(mx, vv);
            }
            #pragma unroll
            for (int off = 8; off; off >>= 1)
                mx = fmaxf(mx, __shfl_xor_sync(0xffffffffu, mx, off, 16));
            float mn = fmaxf(mS[rr], mx);
            float f  = __expf(mS[rr] - mn);     // 0 on first real tile (underflow), exact
            mS[rr] = mn;
            float rs = 0.f;
            #pragma unroll
            for (int cc = 0; cc < 4; cc++) {
                float p = (vals[cc] > -1e29f) ? __expf(vals[cc] - mn) : 0.f;  // masked -> exactly 0
                rs += p;
                Ps[(tx4 + cc) * 65 + ty4 + rr] = p;   // transposed store
            }
            #pragma unroll
            for (int off = 8; off; off >>= 1)
                rs += __shfl_xor_sync(0xffffffffu, rs, off, 16);
            lS[rr] = lS[rr] * f + rs;
            o[rr][0] *= f; o[rr][1] *= f; o[rr][2] *= f; o[rr][3] *= f;
        }
        __syncthreads();   // Ps visible

        // ---- O += P V ----
        #pragma unroll 4
        for (int j = 0; j < 64; j++) {
            float p0 = Ps[j * 65 + ty4 + 0];
            float p1 = Ps[j * 65 + ty4 + 1];
            float p2 = Ps[j * 65 + ty4 + 2];
            float p3 = Ps[j * 65 + ty4 + 3];
            float v0 = Vs[j * 65 + tx4 + 0];
            float v1 = Vs[j * 65 + tx4 + 1];
            float v2 = Vs[j * 65 + tx4 + 2];
            float v3 = Vs[j * 65 + tx4 + 3];
            o[0][0] = fmaf(p0, v0, o[0][0]); o[0][1] = fmaf(p0, v1, o[0][1]);
            o[0][2] = fmaf(p0, v2, o[0][2]); o[0][3] = fmaf(p0, v3, o[0][3]);
            o[1][0] = fmaf(p1, v0, o[1][0]); o[1][1] = fmaf(p1, v1, o[1][1]);
            o[1][2] = fmaf(p1, v2, o[1][2]); o[1][3] = fmaf(p1, v3, o[1][3]);
            o[2][0] = fmaf(p2, v0, o[2][0]); o[2][1] = fmaf(p2, v1, o[2][1]);
            o[2][2] = fmaf(p2, v2, o[2][2]); o[2][3] = fmaf(p2, v3, o[2][3]);
            o[3][0] = fmaf(p3, v0, o[3][0]); o[3][1] = fmaf(p3, v1, o[3][1]);
            o[3][2] = fmaf(p3, v2, o[3][2]); o[3][3] = fmaf(p3, v3, o[3][3]);
        }
        __syncthreads();   // PV done before next tile's loads overwrite Ks/Vs/Ps
    }

    // ---- epilogue: O / l, write [N, H*D] node-major ----
    #pragma unroll
    for (int rr = 0; rr < 4; rr++) {
        float inv = 1.f / lS[rr];
        float4 w4 = make_float4(o[rr][0] * inv, o[rr][1] * inv,
                                o[rr][2] * inv, o[rr][3] * inv);
        *(float4*)(g_att + (size_t)(q0 + ty4 + rr) * FDIM + h * HD + tx4) = w4;
    }
}

// ---------------- launch ----------------
extern "C" void kernel_launch(void* const* d_in, const int* in_sizes, int n_in,
                              void* d_out, int out_size) {
    const float* x   = (const float*)d_in[0];
    const int*   ei  = (const int*)d_in[1];
    const int*   et  = (const int*)d_in[2];
    const float* etw = (const float*)d_in[3];
    const float* wq  = (const float*)d_in[4];
    const float* bq  = (const float*)d_in[5];
    const float* wk  = (const float*)d_in[6];
    const float* bk  = (const float*)d_in[7];
    const float* wv  = (const float*)d_in[8];
    const float* bv  = (const float*)d_in[9];
    const float* wiq = (const float*)d_in[10];
    const float* biq = (const float*)d_in[11];
    const float* wik = (const float*)d_in[12];
    const float* bik = (const float*)d_in[13];
    const float* wiv = (const float*)d_in[14];
    const float* biv = (const float*)d_in[15];
    const float* wo  = (const float*)d_in[16];
    const float* bo  = (const float*)d_in[17];
    float* out = (float*)d_out;

    float *pq, *pk, *pv, *pq2, *pk2, *pv2, *patt;
    cudaGetSymbolAddress((void**)&pq,   g_q);
    cudaGetSymbolAddress((void**)&pk,   g_k);
    cudaGetSymbolAddress((void**)&pv,   g_v);
    cudaGetSymbolAddress((void**)&pq2,  g_q2);
    cudaGetSymbolAddress((void**)&pk2,  g_k2);
    cudaGetSymbolAddress((void**)&pv2,  g_v2);
    cudaGetSymbolAddress((void**)&patt, g_att);

    const int ZT = (NN * NN / 4 + 255) / 256;
    zero_cells_kernel<<<ZT, 256>>>();
    scatter_kernel<<<(EE + 255) / 256, 256>>>(ei, et);
    build_mask_kernel<<<ZT, 256>>>();

    dim3 gg(8, 24);   // (N/128, M/128)
    gemm_bias_kernel<<<gg, 256>>>(x,  wq,  bq,  pq);
    gemm_bias_kernel<<<gg, 256>>>(x,  wk,  bk,  pk);
    gemm_bias_kernel<<<gg, 256>>>(x,  wv,  bv,  pv);
    gemm_bias_kernel<<<gg, 256>>>(pq, wiq, biq, pq2);
    gemm_bias_kernel<<<gg, 256>>>(pk, wik, bik, pk2);
    gemm_bias_kernel<<<gg, 256>>>(pv, wiv, biv, pv2);

    cudaFuncSetAttribute(attn_kernel, cudaFuncAttributeMaxDynamicSharedMemorySize,
                         ATTN_SMEM_BYTES);
    attn_kernel<<<dim3(48, 16), 256, ATTN_SMEM_BYTES>>>(etw);

    gemm_bias_kernel<<<gg, 256>>>(patt, wo, bo, out);
}

// round 4
// speedup vs baseline: 1.8066x; 1.8066x over previous
#include <cuda_runtime.h>
#include <math.h>

#define NN     3072
#define EE     98304
#define FDIM   1024
#define HD     64
#define MAXDEG 256

// ---------------- scratch (static device arrays; no allocation) ----------------
__device__ int   g_cell[NN * NN];        // packed (edge_id<<3)|etype, 0 = no edge
__device__ int   g_adj[NN * MAXDEG];     // packed col | (code<<20)
__device__ int   g_deg[NN];
__device__ float g_q [NN * FDIM];
__device__ float g_k [NN * FDIM];
__device__ float g_v [NN * FDIM];
__device__ float g_q2[NN * FDIM];
__device__ float g_k2[NN * FDIM];
__device__ float g_v2[NN * FDIM];
__device__ float g_att[NN * FDIM];

// ---------------- mask / adjacency construction ----------------
__global__ void zero_cells_kernel() {
    int i = blockIdx.x * blockDim.x + threadIdx.x;     // over NN*NN/4 int4
    if (i < NN * NN / 4) {
        ((int4*)g_cell)[i] = make_int4(0, 0, 0, 0);
    }
}

__global__ void scatter_kernel(const int* __restrict__ ei, const int* __restrict__ et) {
    int e = blockIdx.x * blockDim.x + threadIdx.x;
    if (e < EE) {
        int s = ei[e];
        int d = ei[EE + e];
        int val = (e << 3) | et[e];                    // etype 1..4 (3 bits); max edge-id = last-wins
        atomicMax(&g_cell[s * NN + d], val);
    }
}

// One block per row: compact valid entries (edges + self-loop) into adjacency list.
__global__ __launch_bounds__(256) void csr_build_kernel() {
    const int n = blockIdx.x;
    __shared__ int cnt;
    if (threadIdx.x == 0) cnt = 0;
    __syncthreads();

    const int4* row = (const int4*)(g_cell + (size_t)n * NN);
    for (int c4 = threadIdx.x; c4 < NN / 4; c4 += 256) {
        int4 c = row[c4];
        int cb = c4 * 4;
        int vals[4] = {c.x, c.y, c.z, c.w};
        #pragma unroll
        for (int u = 0; u < 4; u++) {
            int col  = cb + u;
            int code = vals[u] ? (vals[u] & 7) : ((col == n) ? 4 : 0);
            if (code) {
                int pos = atomicAdd(&cnt, 1);
                if (pos < MAXDEG) g_adj[n * MAXDEG + pos] = col | (code << 20);
            }
        }
    }
    __syncthreads();
    if (threadIdx.x == 0) g_deg[n] = (cnt < MAXDEG) ? cnt : MAXDEG;
}

// ---------------- fp32 GEMM: Y[M,N] = X[M,K] @ W[N,K]^T + bias ----------------
// Fixed M=3072, N=1024, K=1024. Tile 128x128xBK16, 256 threads, 8x8/thread.
__global__ __launch_bounds__(256) void gemm_bias_kernel(
    const float* __restrict__ X, const float* __restrict__ W,
    const float* __restrict__ bias, float* __restrict__ Y)
{
    const int K = 1024, NC = 1024;
    __shared__ float As[16][132];
    __shared__ float Bs[16][132];

    const int tid  = threadIdx.x;
    const int tx   = tid & 15;
    const int ty   = tid >> 4;
    const int row0 = blockIdx.y << 7;
    const int col0 = blockIdx.x << 7;
    const int lr   = tid >> 2;          // 0..63
    const int lc   = (tid & 3) << 2;    // 0,4,8,12

    const float* Xp = X + (size_t)(row0 + lr) * K + lc;
    const float* Wp = W + (size_t)(col0 + lr) * K + lc;

    float acc[8][8];
    #pragma unroll
    for (int i = 0; i < 8; i++)
        #pragma unroll
        for (int j = 0; j < 8; j++) acc[i][j] = 0.f;

    for (int k0 = 0; k0 < K; k0 += 16) {
        float4 xa = *(const float4*)(Xp + k0);
        float4 xb = *(const float4*)(Xp + (size_t)64 * K + k0);
        float4 wa = *(const float4*)(Wp + k0);
        float4 wb = *(const float4*)(Wp + (size_t)64 * K + k0);
        As[lc+0][lr]    = xa.x; As[lc+1][lr]    = xa.y; As[lc+2][lr]    = xa.z; As[lc+3][lr]    = xa.w;
        As[lc+0][lr+64] = xb.x; As[lc+1][lr+64] = xb.y; As[lc+2][lr+64] = xb.z; As[lc+3][lr+64] = xb.w;
        Bs[lc+0][lr]    = wa.x; Bs[lc+1][lr]    = wa.y; Bs[lc+2][lr]    = wa.z; Bs[lc+3][lr]    = wa.w;
        Bs[lc+0][lr+64] = wb.x; Bs[lc+1][lr+64] = wb.y; Bs[lc+2][lr+64] = wb.z; Bs[lc+3][lr+64] = wb.w;
        __syncthreads();

        #pragma unroll
        for (int kk = 0; kk < 16; kk++) {
            float a[8], b[8];
            *(float4*)(a)     = *(const float4*)&As[kk][ty * 8];
            *(float4*)(a + 4) = *(const float4*)&As[kk][ty * 8 + 4];
            *(float4*)(b)     = *(const float4*)&Bs[kk][tx * 8];
            *(float4*)(b + 4) = *(const float4*)&Bs[kk][tx * 8 + 4];
            #pragma unroll
            for (int i = 0; i < 8; i++)
                #pragma unroll
                for (int j = 0; j < 8; j++)
                    acc[i][j] = fmaf(a[i], b[j], acc[i][j]);
        }
        __syncthreads();
    }

    float bv[8];
    *(float4*)(bv)     = *(const float4*)&bias[col0 + tx * 8];
    *(float4*)(bv + 4) = *(const float4*)&bias[col0 + tx * 8 + 4];
    #pragma unroll
    for (int i = 0; i < 8; i++) {
        float* yp = Y + (size_t)(row0 + ty * 8 + i) * NC + col0 + tx * 8;
        float4 o1 = make_float4(acc[i][0] + bv[0], acc[i][1] + bv[1],
                                acc[i][2] + bv[2], acc[i][3] + bv[3]);
        float4 o2 = make_float4(acc[i][4] + bv[4], acc[i][5] + bv[5],
                                acc[i][6] + bv[6], acc[i][7] + bv[7]);
        *(float4*)yp       = o1;
        *(float4*)(yp + 4) = o2;
    }
}

// ---------------- sparse gather attention ----------------
// One block per node (512 threads = 16 warps, warp h = head h).
// Softmax support = neighbor list exactly (matches masked dense softmax).
__global__ __launch_bounds__(512) void attn_sparse_kernel(const float* __restrict__ etw)
{
    __shared__ float q_s[FDIM];            // this node's full q2 row
    __shared__ int   nbr_s[MAXDEG];        // packed col | code<<20
    __shared__ float sc_s[16][MAXDEG];     // per-head scores -> probs
    __shared__ float wsh_s[8];             // wsh[1..4] = softplus(etw[0..3])

    const int n    = blockIdx.x;
    const int tid  = threadIdx.x;
    const int h    = tid >> 5;
    const int lane = tid & 31;

    if (tid < 4) wsh_s[tid + 1] = log1pf(expf(etw[tid]));

    ((float2*)q_s)[tid] = ((const float2*)(g_q2 + (size_t)n * FDIM))[tid];

    const int deg = g_deg[n];
    for (int j = tid; j < deg; j += 512) nbr_s[j] = g_adj[n * MAXDEG + j];
    __syncthreads();

    // preload this head's q slice into registers (broadcast smem reads)
    float4 qv[16];
    #pragma unroll
    for (int i = 0; i < 16; i++) qv[i] = *(const float4*)&q_s[h * HD + i * 4];

    // ---- scores: lanes parallel over neighbors ----
    float mx = -1e30f;
    for (int base = 0; base < deg; base += 32) {
        int   j = base + lane;
        float s = -1e30f;
        if (j < deg) {
            int pk   = nbr_s[j];
            int m    = pk & 0xFFFFF;
            int code = pk >> 20;
            const float4* kp = (const float4*)(g_k2 + (size_t)m * FDIM + h * HD);
            float a0 = 0.f, a1 = 0.f, a2 = 0.f, a3 = 0.f;
            #pragma unroll
            for (int i = 0; i < 16; i += 4) {
                float4 k0 = kp[i + 0], k1 = kp[i + 1], k2 = kp[i + 2], k3 = kp[i + 3];
                a0 = fmaf(qv[i+0].x, k0.x, a0); a0 = fmaf(qv[i+0].y, k0.y, a0);
                a0 = fmaf(qv[i+0].z, k0.z, a0); a0 = fmaf(qv[i+0].w, k0.w, a0);
                a1 = fmaf(qv[i+1].x, k1.x, a1); a1 = fmaf(qv[i+1].y, k1.y, a1);
                a1 = fmaf(qv[i+1].z, k1.z, a1); a1 = fmaf(qv[i+1].w, k1.w, a1);
                a2 = fmaf(qv[i+2].x, k2.x, a2); a2 = fmaf(qv[i+2].y, k2.y, a2);
                a2 = fmaf(qv[i+2].z, k2.z, a2); a2 = fmaf(qv[i+2].w, k2.w, a2);
                a3 = fmaf(qv[i+3].x, k3.x, a3); a3 = fmaf(qv[i+3].y, k3.y, a3);
                a3 = fmaf(qv[i+3].z, k3.z, a3); a3 = fmaf(qv[i+3].w, k3.w, a3);
            }
            float acc = (a0 + a1) + (a2 + a3);
            s = fmaf(acc, 0.125f, wsh_s[code]);     // scale = 1/sqrt(64)
            sc_s[h][j] = s;
        }
        mx = fmaxf(mx, s);
    }
    #pragma unroll
    for (int off = 16; off; off >>= 1)
        mx = fmaxf(mx, __shfl_xor_sync(0xffffffffu, mx, off));
    __syncwarp();

    // ---- softmax over the list ----
    float sum = 0.f;
    for (int j = lane; j < deg; j += 32) {
        float p = __expf(sc_s[h][j] - mx);
        sc_s[h][j] = p;
        sum += p;
    }
    #pragma unroll
    for (int off = 16; off; off >>= 1)
        sum += __shfl_xor_sync(0xffffffffu, sum, off);
    const float inv = 1.f / sum;
    __syncwarp();

    // ---- PV: lanes parallel over dims, serial (pipelined) over neighbors ----
    const int dof = h * HD + lane * 2;
    float o0 = 0.f, o1 = 0.f;
    #pragma unroll 4
    for (int j = 0; j < deg; j++) {
        int   m = nbr_s[j] & 0xFFFFF;
        float p = sc_s[h][j];
        float2 vv = *(const float2*)(g_v2 + (size_t)m * FDIM + dof);
        o0 = fmaf(p, vv.x, o0);
        o1 = fmaf(p, vv.y, o1);
    }
    *(float2*)(g_att + (size_t)n * FDIM + dof) = make_float2(o0 * inv, o1 * inv);
}

// ---------------- launch ----------------
extern "C" void kernel_launch(void* const* d_in, const int* in_sizes, int n_in,
                              void* d_out, int out_size) {
    const float* x   = (const float*)d_in[0];
    const int*   ei  = (const int*)d_in[1];
    const int*   et  = (const int*)d_in[2];
    const float* etw = (const float*)d_in[3];
    const float* wq  = (const float*)d_in[4];
    const float* bq  = (const float*)d_in[5];
    const float* wk  = (const float*)d_in[6];
    const float* bk  = (const float*)d_in[7];
    const float* wv  = (const float*)d_in[8];
    const float* bv  = (const float*)d_in[9];
    const float* wiq = (const float*)d_in[10];
    const float* biq = (const float*)d_in[11];
    const float* wik = (const float*)d_in[12];
    const float* bik = (const float*)d_in[13];
    const float* wiv = (const float*)d_in[14];
    const float* biv = (const float*)d_in[15];
    const float* wo  = (const float*)d_in[16];
    const float* bo  = (const float*)d_in[17];
    float* out = (float*)d_out;

    float *pq, *pk, *pv, *pq2, *pk2, *pv2, *patt;
    cudaGetSymbolAddress((void**)&pq,   g_q);
    cudaGetSymbolAddress((void**)&pk,   g_k);
    cudaGetSymbolAddress((void**)&pv,   g_v);
    cudaGetSymbolAddress((void**)&pq2,  g_q2);
    cudaGetSymbolAddress((void**)&pk2,  g_k2);
    cudaGetSymbolAddress((void**)&pv2,  g_v2);
    cudaGetSymbolAddress((void**)&patt, g_att);

    const int ZT = (NN * NN / 4 + 255) / 256;
    zero_cells_kernel<<<ZT, 256>>>();
    scatter_kernel<<<(EE + 255) / 256, 256>>>(ei, et);
    csr_build_kernel<<<NN, 256>>>();

    dim3 gg(8, 24);   // (N/128, M/128)
    gemm_bias_kernel<<<gg, 256>>>(x,  wq,  bq,  pq);
    gemm_bias_kernel<<<gg, 256>>>(x,  wk,  bk,  pk);
    gemm_bias_kernel<<<gg, 256>>>(x,  wv,  bv,  pv);
    gemm_bias_kernel<<<gg, 256>>>(pq, wiq, biq, pq2);
    gemm_bias_kernel<<<gg, 256>>>(pk, wik, bik, pk2);
    gemm_bias_kernel<<<gg, 256>>>(pv, wiv, biv, pv2);

    attn_sparse_kernel<<<NN, 512>>>(etw);

    gemm_bias_kernel<<<gg, 256>>>(patt, wo, bo, out);
}

// round 6
// speedup vs baseline: 2.3651x; 1.3091x over previous
#include <cuda_runtime.h>
#include <cuda_bf16.h>
#include <math.h>
#include <stdint.h>

#define NN     3072
#define EE     98304
#define FDIM   1024
#define HD     64
#define MAXDEG 256
#define KEFF   3072      // 3*FDIM: [hi|hi|lo] x [hi|lo|hi]
#define NTILES (KEFF / 32)   // 96 BK32 tiles

// ---------------- scratch (static device arrays; no allocation) ----------------
__device__ int   g_cell[NN * NN];
__device__ int   g_adj[NN * MAXDEG];
__device__ int   g_deg[NN];
__device__ float g_q [NN * FDIM];
__device__ float g_k [NN * FDIM];
__device__ float g_v [NN * FDIM];
__device__ float g_q2[NN * FDIM];
__device__ float g_k2[NN * FDIM];
__device__ float g_v2[NN * FDIM];
__device__ float g_att[NN * FDIM];
__device__ __nv_bfloat16 g_ab[NN * KEFF];          // activation split [M, 3K]
__device__ __nv_bfloat16 g_wb[7 * FDIM * KEFF];    // 7 weight splits [N, 3K]

// ---------------- PTX helpers ----------------
__device__ __forceinline__ uint32_t smem_u32(const void* p) {
    uint32_t a;
    asm("{ .reg .u64 t; cvta.to.shared.u64 t, %1; cvt.u32.u64 %0, t; }" : "=r"(a) : "l"(p));
    return a;
}
__device__ __forceinline__ void cp16(uint32_t dst, const void* src) {
    asm volatile("cp.async.cg.shared.global [%0], [%1], 16;" :: "r"(dst), "l"(src));
}
__device__ __forceinline__ void ldsm4(uint32_t* r, uint32_t a) {
    asm volatile("ldmatrix.sync.aligned.m8n8.x4.shared.b16 {%0,%1,%2,%3}, [%4];"
                 : "=r"(r[0]), "=r"(r[1]), "=r"(r[2]), "=r"(r[3]) : "r"(a));
}
__device__ __forceinline__ void ldsm2(uint32_t* r, uint32_t a) {
    asm volatile("ldmatrix.sync.aligned.m8n8.x2.shared.b16 {%0,%1}, [%2];"
                 : "=r"(r[0]), "=r"(r[1]) : "r"(a));
}
__device__ __forceinline__ void mma16816(float* c, const uint32_t* a, const uint32_t* b) {
    asm volatile(
        "mma.sync.aligned.m16n8k16.row.col.f32.bf16.bf16.f32 "
        "{%0,%1,%2,%3}, {%4,%5,%6,%7}, {%8,%9}, {%0,%1,%2,%3};"
        : "+f"(c[0]), "+f"(c[1]), "+f"(c[2]), "+f"(c[3])
        : "r"(a[0]), "r"(a[1]), "r"(a[2]), "r"(a[3]), "r"(b[0]), "r"(b[1]));
}

// ---------------- mask / adjacency construction ----------------
__global__ void zero_cells_kernel() {
    int i = blockIdx.x * blockDim.x + threadIdx.x;
    if (i < NN * NN / 4) ((int4*)g_cell)[i] = make_int4(0, 0, 0, 0);
}

__global__ void scatter_kernel(const int* __restrict__ ei, const int* __restrict__ et) {
    int e = blockIdx.x * blockDim.x + threadIdx.x;
    if (e < EE) {
        int s = ei[e], d = ei[EE + e];
        atomicMax(&g_cell[s * NN + d], (e << 3) | et[e]);   // max edge-id = last-wins
    }
}

__global__ __launch_bounds__(256) void csr_build_kernel() {
    const int n = blockIdx.x;
    __shared__ int cnt;
    if (threadIdx.x == 0) cnt = 0;
    __syncthreads();
    const int4* row = (const int4*)(g_cell + (size_t)n * NN);
    for (int c4 = threadIdx.x; c4 < NN / 4; c4 += 256) {
        int4 c = row[c4];
        int cb = c4 * 4;
        int vals[4] = {c.x, c.y, c.z, c.w};
        #pragma unroll
        for (int u = 0; u < 4; u++) {
            int col  = cb + u;
            int code = vals[u] ? (vals[u] & 7) : ((col == n) ? 4 : 0);
            if (code) {
                int pos = atomicAdd(&cnt, 1);
                if (pos < MAXDEG) g_adj[n * MAXDEG + pos] = col | (code << 20);
            }
        }
    }
    __syncthreads();
    if (threadIdx.x == 0) g_deg[n] = (cnt < MAXDEG) ? cnt : MAXDEG;
}

// ---------------- fp32 -> bf16 hi/lo split ----------------
// Activation layout per row: [hi | hi | lo]. Weight layout per row: [hi | lo | hi].
__global__ __launch_bounds__(256) void conv_act_kernel(const float* __restrict__ X,
                                                       __nv_bfloat16* __restrict__ A) {
    int i = blockIdx.x * 256 + threadIdx.x;      // over NN*FDIM/4
    if (i >= NN * FDIM / 4) return;
    float4 v = ((const float4*)X)[i];
    int m = i >> 8;
    int c = (i & 255) << 2;
    __nv_bfloat162 h01, h23, l01, l23;
    h01.x = __float2bfloat16(v.x); h01.y = __float2bfloat16(v.y);
    h23.x = __float2bfloat16(v.z); h23.y = __float2bfloat16(v.w);
    l01.x = __float2bfloat16(v.x - __bfloat162float(h01.x));
    l01.y = __float2bfloat16(v.y - __bfloat162float(h01.y));
    l23.x = __float2bfloat16(v.z - __bfloat162float(h23.x));
    l23.y = __float2bfloat16(v.w - __bfloat162float(h23.y));
    __nv_bfloat16* row = A + (size_t)m * KEFF + c;
    *(__nv_bfloat162*)(row)        = h01; *(__nv_bfloat162*)(row + 2)    = h23;
    *(__nv_bfloat162*)(row + 1024) = h01; *(__nv_bfloat162*)(row + 1026) = h23;
    *(__nv_bfloat162*)(row + 2048) = l01; *(__nv_bfloat162*)(row + 2050) = l23;
}

__global__ __launch_bounds__(256) void conv_w_kernel(const float* __restrict__ W,
                                                     __nv_bfloat16* __restrict__ B) {
    int i = blockIdx.x * 256 + threadIdx.x;      // over FDIM*FDIM/4
    if (i >= FDIM * FDIM / 4) return;
    float4 v = ((const float4*)W)[i];
    int n = i >> 8;
    int c = (i & 255) << 2;
    __nv_bfloat162 h01, h23, l01, l23;
    h01.x = __float2bfloat16(v.x); h01.y = __float2bfloat16(v.y);
    h23.x = __float2bfloat16(v.z); h23.y = __float2bfloat16(v.w);
    l01.x = __float2bfloat16(v.x - __bfloat162float(h01.x));
    l01.y = __float2bfloat16(v.y - __bfloat162float(h01.y));
    l23.x = __float2bfloat16(v.z - __bfloat162float(h23.x));
    l23.y = __float2bfloat16(v.w - __bfloat162float(h23.y));
    __nv_bfloat16* row = B + (size_t)n * KEFF + c;
    *(__nv_bfloat162*)(row)        = h01; *(__nv_bfloat162*)(row + 2)    = h23;
    *(__nv_bfloat162*)(row + 1024) = l01; *(__nv_bfloat162*)(row + 1026) = l23;
    *(__nv_bfloat162*)(row + 2048) = h01; *(__nv_bfloat162*)(row + 2050) = h23;
}

// ---------------- mma.sync bf16 GEMM: Y[3072,1024] = A'[3072,3072] @ B'[1024,3072]^T + bias
// CTA tile 128x128xBK32, 8 warps (2M x 4N), warp tile 64x32, 3-stage cp.async.
// Smem layout: 8x8-elem tile atoms of 128B: addr = (m8*4 + k8)*128 + r*16
// -> conflict-free cp.async writes AND ldmatrix reads.
#define STAGE_BYTES 16384               // A 8KB + B 8KB
#define GEMM_SMEM   (3 * STAGE_BYTES)   // 49152

__device__ __forceinline__ void load_tile_pair(
    const __nv_bfloat16* Abase, const __nv_bfloat16* Bbase,
    int row0, int col0, int k0, uint32_t sA, uint32_t sB, int tid)
{
    #pragma unroll
    for (int i = 0; i < 2; i++) {
        int c   = tid + i * 256;         // 0..511
        int row = c >> 2;
        int kc  = c & 3;
        uint32_t soff = (uint32_t)(((row >> 3) * 4 + kc) * 128 + (row & 7) * 16);
        cp16(sA + soff, Abase + (size_t)(row0 + row) * KEFF + k0 + kc * 8);
        cp16(sB + soff, Bbase + (size_t)(col0 + row) * KEFF + k0 + kc * 8);
    }
}

__global__ __launch_bounds__(256) void gemm_mma_kernel(
    const __nv_bfloat16* __restrict__ A, const __nv_bfloat16* __restrict__ B,
    const float* __restrict__ bias, float* __restrict__ Y)
{
    extern __shared__ char smem[];
    const uint32_t sb = smem_u32(smem);
    const int tid  = threadIdx.x;
    const int wid  = tid >> 5;
    const int lane = tid & 31;
    const int wm   = wid & 1;            // 2 warps along M (64 rows each)
    const int wn   = wid >> 1;           // 4 warps along N (32 cols each)
    const int row0 = blockIdx.y << 7;
    const int col0 = blockIdx.x << 7;

    const int g  = lane >> 3;            // ldmatrix sub-tile group 0..3
    const int r8 = lane & 7;
    // A: addr = Abuf + (m8*4 + k8)*128 + r*16 ; m8 = wm*8 + 2*mt + (g&1), k8 = 2*kt + (g>>1)
    const uint32_t aconst = (uint32_t)((wm * 8 + (g & 1)) * 512 + (g >> 1) * 128 + r8 * 16);
    // B: n8 = wn*4 + nt, k8 = 2*kt + (g&1)  (lanes 16-31 mirror 0-15)
    const uint32_t bconst = (uint32_t)(wn * 4 * 512 + (g & 1) * 128 + r8 * 16);

    float acc[4][4][4];
    #pragma unroll
    for (int mt = 0; mt < 4; mt++)
        #pragma unroll
        for (int nt = 0; nt < 4; nt++)
            acc[mt][nt][0] = acc[mt][nt][1] = acc[mt][nt][2] = acc[mt][nt][3] = 0.f;

    // prologue: stages 0,1 in flight
    load_tile_pair(A, B, row0, col0, 0, sb, sb + 8192, tid);
    asm volatile("cp.async.commit_group;" ::: "memory");
    load_tile_pair(A, B, row0, col0, 32, sb + STAGE_BYTES, sb + STAGE_BYTES + 8192, tid);
    asm volatile("cp.async.commit_group;" ::: "memory");

    int buf = 0;
    for (int t = 0; t < NTILES; t++) {
        asm volatile("cp.async.wait_group 1;" ::: "memory");
        __syncthreads();

        // issue load for tile t+2 into the buffer freed by tile t-1
        int nbuf = buf + 1; if (nbuf == 3) nbuf = 0;
        int lbuf = nbuf + 1; if (lbuf == 3) lbuf = 0;
        if (t + 2 < NTILES) {
            uint32_t ls = sb + (uint32_t)lbuf * STAGE_BYTES;
            load_tile_pair(A, B, row0, col0, (t + 2) * 32, ls, ls + 8192, tid);
        }
        asm volatile("cp.async.commit_group;" ::: "memory");

        const uint32_t Ab = sb + (uint32_t)buf * STAGE_BYTES;
        const uint32_t Bb = Ab + 8192;
        #pragma unroll
        for (int kt = 0; kt < 2; kt++) {
            uint32_t af[4][4], bfr[4][2];
            #pragma unroll
            for (int mt = 0; mt < 4; mt++)
                ldsm4(af[mt], Ab + aconst + (uint32_t)(mt * 1024 + kt * 256));
            #pragma unroll
            for (int nt = 0; nt < 4; nt++)
                ldsm2(bfr[nt], Bb + bconst + (uint32_t)(nt * 512 + kt * 256));
            #pragma unroll
            for (int mt = 0; mt < 4; mt++)
                #pragma unroll
                for (int nt = 0; nt < 4; nt++)
                    mma16816(acc[mt][nt], af[mt], bfr[nt]);
        }
        buf = nbuf;
    }

    // epilogue: canonical c-fragment mapping, add bias, float2 stores
    const int mbase = row0 + wm * 64 + (lane >> 2);
    const int nbase = col0 + wn * 32 + (lane & 3) * 2;
    #pragma unroll
    for (int mt = 0; mt < 4; mt++) {
        #pragma unroll
        for (int nt = 0; nt < 4; nt++) {
            int m = mbase + mt * 16;
            int n = nbase + nt * 8;
            float2 b2 = *(const float2*)&bias[n];
            *(float2*)&Y[(size_t)m * FDIM + n] =
                make_float2(acc[mt][nt][0] + b2.x, acc[mt][nt][1] + b2.y);
            *(float2*)&Y[(size_t)(m + 8) * FDIM + n] =
                make_float2(acc[mt][nt][2] + b2.x, acc[mt][nt][3] + b2.y);
        }
    }
}

// ---------------- sparse gather attention (unchanged) ----------------
__global__ __launch_bounds__(512) void attn_sparse_kernel(const float* __restrict__ etw)
{
    __shared__ float q_s[FDIM];
    __shared__ int   nbr_s[MAXDEG];
    __shared__ float sc_s[16][MAXDEG];
    __shared__ float wsh_s[8];

    const int n    = blockIdx.x;
    const int tid  = threadIdx.x;
    const int h    = tid >> 5;
    const int lane = tid & 31;

    if (tid < 4) wsh_s[tid + 1] = log1pf(expf(etw[tid]));
    ((float2*)q_s)[tid] = ((const float2*)(g_q2 + (size_t)n * FDIM))[tid];
    const int deg = g_deg[n];
    for (int j = tid; j < deg; j += 512) nbr_s[j] = g_adj[n * MAXDEG + j];
    __syncthreads();

    float4 qv[16];
    #pragma unroll
    for (int i = 0; i < 16; i++) qv[i] = *(const float4*)&q_s[h * HD + i * 4];

    float mx = -1e30f;
    for (int base = 0; base < deg; base += 32) {
        int   j = base + lane;
        float s = -1e30f;
        if (j < deg) {
            int pk   = nbr_s[j];
            int m    = pk & 0xFFFFF;
            int code = pk >> 20;
            const float4* kp = (const float4*)(g_k2 + (size_t)m * FDIM + h * HD);
            float a0 = 0.f, a1 = 0.f, a2 = 0.f, a3 = 0.f;
            #pragma unroll
            for (int i = 0; i < 16; i += 4) {
                float4 k0 = kp[i + 0], k1 = kp[i + 1], k2 = kp[i + 2], k3 = kp[i + 3];
                a0 = fmaf(qv[i+0].x, k0.x, a0); a0 = fmaf(qv[i+0].y, k0.y, a0);
                a0 = fmaf(qv[i+0].z, k0.z, a0); a0 = fmaf(qv[i+0].w, k0.w, a0);
                a1 = fmaf(qv[i+1].x, k1.x, a1); a1 = fmaf(qv[i+1].y, k1.y, a1);
                a1 = fmaf(qv[i+1].z, k1.z, a1); a1 = fmaf(qv[i+1].w, k1.w, a1);
                a2 = fmaf(qv[i+2].x, k2.x, a2); a2 = fmaf(qv[i+2].y, k2.y, a2);
                a2 = fmaf(qv[i+2].z, k2.z, a2); a2 = fmaf(qv[i+2].w, k2.w, a2);
                a3 = fmaf(qv[i+3].x, k3.x, a3); a3 = fmaf(qv[i+3].y, k3.y, a3);
                a3 = fmaf(qv[i+3].z, k3.z, a3); a3 = fmaf(qv[i+3].w, k3.w, a3);
            }
            float acc = (a0 + a1) + (a2 + a3);
            s = fmaf(acc, 0.125f, wsh_s[code]);
            sc_s[h][j] = s;
        }
        mx = fmaxf(mx, s);
    }
    #pragma unroll
    for (int off = 16; off; off >>= 1)
        mx = fmaxf(mx, __shfl_xor_sync(0xffffffffu, mx, off));
    __syncwarp();

    float sum = 0.f;
    for (int j = lane; j < deg; j += 32) {
        float p = __expf(sc_s[h][j] - mx);
        sc_s[h][j] = p;
        sum += p;
    }
    #pragma unroll
    for (int off = 16; off; off >>= 1)
        sum += __shfl_xor_sync(0xffffffffu, sum, off);
    const float inv = 1.f / sum;
    __syncwarp();

    const int dof = h * HD + lane * 2;
    float o0 = 0.f, o1 = 0.f;
    #pragma unroll 4
    for (int j = 0; j < deg; j++) {
        int   m = nbr_s[j] & 0xFFFFF;
        float p = sc_s[h][j];
        float2 vv = *(const float2*)(g_v2 + (size_t)m * FDIM + dof);
        o0 = fmaf(p, vv.x, o0);
        o1 = fmaf(p, vv.y, o1);
    }
    *(float2*)(g_att + (size_t)n * FDIM + dof) = make_float2(o0 * inv, o1 * inv);
}

// ---------------- launch ----------------
extern "C" void kernel_launch(void* const* d_in, const int* in_sizes, int n_in,
                              void* d_out, int out_size) {
    const float* x   = (const float*)d_in[0];
    const int*   ei  = (const int*)d_in[1];
    const int*   et  = (const int*)d_in[2];
    const float* etw = (const float*)d_in[3];
    const float* W[7]  = {(const float*)d_in[4],  (const float*)d_in[6],
                          (const float*)d_in[8],  (const float*)d_in[10],
                          (const float*)d_in[12], (const float*)d_in[14],
                          (const float*)d_in[16]};
    const float* Bs[7] = {(const float*)d_in[5],  (const float*)d_in[7],
                          (const float*)d_in[9],  (const float*)d_in[11],
                          (const float*)d_in[13], (const float*)d_in[15],
                          (const float*)d_in[17]};
    float* out = (float*)d_out;

    float *pq, *pk, *pv, *pq2, *pk2, *pv2, *patt;
    __nv_bfloat16 *pab, *pwb;
    cudaGetSymbolAddress((void**)&pq,   g_q);
    cudaGetSymbolAddress((void**)&pk,   g_k);
    cudaGetSymbolAddress((void**)&pv,   g_v);
    cudaGetSymbolAddress((void**)&pq2,  g_q2);
    cudaGetSymbolAddress((void**)&pk2,  g_k2);
    cudaGetSymbolAddress((void**)&pv2,  g_v2);
    cudaGetSymbolAddress((void**)&patt, g_att);
    cudaGetSymbolAddress((void**)&pab,  g_ab);
    cudaGetSymbolAddress((void**)&pwb,  g_wb);

    cudaFuncSetAttribute(gemm_mma_kernel, cudaFuncAttributeMaxDynamicSharedMemorySize,
                         GEMM_SMEM);

    // mask / adjacency
    const int ZT = (NN * NN / 4 + 255) / 256;
    zero_cells_kernel<<<ZT, 256>>>();
    scatter_kernel<<<(EE + 255) / 256, 256>>>(ei, et);
    csr_build_kernel<<<NN, 256>>>();

    // weight splits
    const int WG = (FDIM * FDIM / 4 + 255) / 256;
    for (int w = 0; w < 7; w++)
        conv_w_kernel<<<WG, 256>>>(W[w], pwb + (size_t)w * FDIM * KEFF);

    const int AG = (NN * FDIM / 4 + 255) / 256;
    dim3 gg(FDIM / 128, NN / 128);    // (8, 24)
    #define GEMM(Ain, widx, bptr, Yout)                                                  \
        gemm_mma_kernel<<<gg, 256, GEMM_SMEM>>>(Ain, pwb + (size_t)(widx) * FDIM * KEFF, \
                                                bptr, Yout)

    conv_act_kernel<<<AG, 256>>>(x, pab);
    GEMM(pab, 0, Bs[0], pq);
    GEMM(pab, 1, Bs[1], pk);
    GEMM(pab, 2, Bs[2], pv);
    conv_act_kernel<<<AG, 256>>>(pq, pab);
    GEMM(pab, 3, Bs[3], pq2);
    conv_act_kernel<<<AG, 256>>>(pk, pab);
    GEMM(pab, 4, Bs[4], pk2);
    conv_act_kernel<<<AG, 256>>>(pv, pab);
    GEMM(pab, 5, Bs[5], pv2);

    attn_sparse_kernel<<<NN, 512>>>(etw);

    conv_act_kernel<<<AG, 256>>>(patt, pab);
    GEMM(pab, 6, Bs[6], out);
    #undef GEMM
}

// round 7
// speedup vs baseline: 3.0922x; 1.3075x over previous
#include <cuda_runtime.h>
#include <cuda_bf16.h>
#include <math.h>
#include <stdint.h>

#define NN     3072
#define EE     98304
#define FDIM   1024
#define HD     64
#define MAXDEG 256
#define KEFF   3072          // 3*FDIM: [hi|hi|lo] x [hi|lo|hi]
#define NTILES (KEFF / 32)   // 96 BK32 tiles
#define WSZ    ((size_t)FDIM * KEFF)

// ---------------- scratch (static device arrays; no allocation) ----------------
__device__ int   g_cnt[NN];
__device__ int   g_ecol[NN * MAXDEG];    // col | code<<20 (raw appended edges)
__device__ int   g_eeid[NN * MAXDEG];    // edge id (for last-wins dedup)
__device__ int   g_adj[NN * MAXDEG];     // deduped col | code<<20
__device__ int   g_deg[NN];
__device__ float g_q2[NN * FDIM];
__device__ float g_k2[NN * FDIM];
__device__ float g_v2[NN * FDIM];
__device__ __nv_bfloat16 g_ab  [NN * KEFF];   // split of x
__device__ __nv_bfloat16 g_abq [NN * KEFF];   // split of q
__device__ __nv_bfloat16 g_abk [NN * KEFF];   // split of k
__device__ __nv_bfloat16 g_abv [NN * KEFF];   // split of v
__device__ __nv_bfloat16 g_abatt[NN * KEFF];  // split of attn output
__device__ __nv_bfloat16 g_wb[7 * WSZ];       // 7 weight splits [N, 3K]

// ---------------- PTX helpers ----------------
__device__ __forceinline__ uint32_t smem_u32(const void* p) {
    uint32_t a;
    asm("{ .reg .u64 t; cvta.to.shared.u64 t, %1; cvt.u32.u64 %0, t; }" : "=r"(a) : "l"(p));
    return a;
}
__device__ __forceinline__ void cp16(uint32_t dst, const void* src) {
    asm volatile("cp.async.cg.shared.global [%0], [%1], 16;" :: "r"(dst), "l"(src));
}
__device__ __forceinline__ void ldsm4(uint32_t* r, uint32_t a) {
    asm volatile("ldmatrix.sync.aligned.m8n8.x4.shared.b16 {%0,%1,%2,%3}, [%4];"
                 : "=r"(r[0]), "=r"(r[1]), "=r"(r[2]), "=r"(r[3]) : "r"(a));
}
__device__ __forceinline__ void ldsm2(uint32_t* r, uint32_t a) {
    asm volatile("ldmatrix.sync.aligned.m8n8.x2.shared.b16 {%0,%1}, [%2];"
                 : "=r"(r[0]), "=r"(r[1]) : "r"(a));
}
__device__ __forceinline__ void mma16816(float* c, const uint32_t* a, const uint32_t* b) {
    asm volatile(
        "mma.sync.aligned.m16n8k16.row.col.f32.bf16.bf16.f32 "
        "{%0,%1,%2,%3}, {%4,%5,%6,%7}, {%8,%9}, {%0,%1,%2,%3};"
        : "+f"(c[0]), "+f"(c[1]), "+f"(c[2]), "+f"(c[3])
        : "r"(a[0]), "r"(a[1]), "r"(a[2]), "r"(a[3]), "r"(b[0]), "r"(b[1]));
}

// ---------------- sparse mask / adjacency build ----------------
__global__ void zero_cnt_kernel() {
    int i = blockIdx.x * blockDim.x + threadIdx.x;
    if (i < NN) g_cnt[i] = 0;
}

__global__ void scatter2_kernel(const int* __restrict__ ei, const int* __restrict__ et) {
    int e = blockIdx.x * blockDim.x + threadIdx.x;
    if (e < EE) {
        int s = ei[e], d = ei[EE + e];
        int pos = atomicAdd(&g_cnt[s], 1);
        if (pos < MAXDEG) {
            g_ecol[s * MAXDEG + pos] = d | (et[e] << 20);
            g_eeid[s * MAXDEG + pos] = e;
        }
    }
}

// Per-row dedup (max edge-id wins = sequential last-wins) + self-loop fixup.
__global__ __launch_bounds__(256) void csr2_kernel() {
    const int n   = blockIdx.x;
    const int tid = threadIdx.x;
    __shared__ int scol[MAXDEG], seid[MAXDEG];
    __shared__ int outc, sflag;
    if (tid == 0) { outc = 0; sflag = 0; }
    int cnt = g_cnt[n];
    if (cnt > MAXDEG) cnt = MAXDEG;
    if (tid < cnt) {
        scol[tid] = g_ecol[n * MAXDEG + tid];
        seid[tid] = g_eeid[n * MAXDEG + tid];
    }
    __syncthreads();
    if (tid < cnt) {
        int cj = scol[tid] & 0xFFFFF;
        int ej = seid[tid];
        bool win = true;
        for (int i = 0; i < cnt; i++)
            if ((scol[i] & 0xFFFFF) == cj && seid[i] > ej) { win = false; break; }
        if (win) {
            int pos = atomicAdd(&outc, 1);
            g_adj[n * MAXDEG + pos] = scol[tid];
            if (cj == n) sflag = 1;
        }
    }
    __syncthreads();
    if (tid == 0) {
        int d = outc;
        if (!sflag && d < MAXDEG) { g_adj[n * MAXDEG + d] = n | (4 << 20); d++; }
        g_deg[n] = d;
    }
}

// ---------------- fp32 -> bf16 hi/lo split ----------------
__device__ __forceinline__ void split2(float y0, float y1, __nv_bfloat16* p) {
    __nv_bfloat162 h, l;
    h.x = __float2bfloat16(y0); h.y = __float2bfloat16(y1);
    l.x = __float2bfloat16(y0 - __bfloat162float(h.x));
    l.y = __float2bfloat16(y1 - __bfloat162float(h.y));
    *(__nv_bfloat162*)(p)        = h;
    *(__nv_bfloat162*)(p + 1024) = h;
    *(__nv_bfloat162*)(p + 2048) = l;
}

__global__ __launch_bounds__(256) void conv_act_kernel(const float* __restrict__ X,
                                                       __nv_bfloat16* __restrict__ A) {
    int i = blockIdx.x * 256 + threadIdx.x;      // over NN*FDIM/4
    if (i >= NN * FDIM / 4) return;
    float4 v = ((const float4*)X)[i];
    int m = i >> 8;
    int c = (i & 255) << 2;
    __nv_bfloat16* row = A + (size_t)m * KEFF + c;
    split2(v.x, v.y, row);
    split2(v.z, v.w, row + 2);
}

struct WPtrs { const float* p[7]; };
__global__ __launch_bounds__(256) void conv_w_all_kernel(WPtrs wp) {
    const int w = blockIdx.y;
    const float* W = wp.p[w];
    __nv_bfloat16* B = g_wb + (size_t)w * WSZ;
    int i = blockIdx.x * 256 + threadIdx.x;      // over FDIM*FDIM/4
    if (i >= FDIM * FDIM / 4) return;
    float4 v = ((const float4*)W)[i];
    int n = i >> 8;
    int c = (i & 255) << 2;
    __nv_bfloat162 h01, h23, l01, l23;
    h01.x = __float2bfloat16(v.x); h01.y = __float2bfloat16(v.y);
    h23.x = __float2bfloat16(v.z); h23.y = __float2bfloat16(v.w);
    l01.x = __float2bfloat16(v.x - __bfloat162float(h01.x));
    l01.y = __float2bfloat16(v.y - __bfloat162float(h01.y));
    l23.x = __float2bfloat16(v.z - __bfloat162float(h23.x));
    l23.y = __float2bfloat16(v.w - __bfloat162float(h23.y));
    __nv_bfloat16* row = B + (size_t)n * KEFF + c;
    *(__nv_bfloat162*)(row)        = h01; *(__nv_bfloat162*)(row + 2)    = h23;
    *(__nv_bfloat162*)(row + 1024) = l01; *(__nv_bfloat162*)(row + 1026) = l23;
    *(__nv_bfloat162*)(row + 2048) = h01; *(__nv_bfloat162*)(row + 2050) = h23;
}

// ---------------- mma.sync bf16 GEMM core ----------------
// CTA tile 128x128xBK32, 8 warps (2M x 4N), 3-stage cp.async.
// Smem atoms: 8x8-elem tiles of 128B: addr = (m8*4 + k8)*128 + r*16.
#define STAGE_BYTES 16384
#define GEMM_SMEM   (3 * STAGE_BYTES)

__device__ __forceinline__ void load_tile_pair(
    const __nv_bfloat16* Abase, const __nv_bfloat16* Bbase,
    int row0, int col0, int k0, uint32_t sA, uint32_t sB, int tid)
{
    #pragma unroll
    for (int i = 0; i < 2; i++) {
        int c   = tid + i * 256;
        int row = c >> 2;
        int kc  = c & 3;
        uint32_t soff = (uint32_t)(((row >> 3) * 4 + kc) * 128 + (row & 7) * 16);
        cp16(sA + soff, Abase + (size_t)(row0 + row) * KEFF + k0 + kc * 8);
        cp16(sB + soff, Bbase + (size_t)(col0 + row) * KEFF + k0 + kc * 8);
    }
}

template<bool SPLIT>
__device__ __forceinline__ void gemm_core(
    const __nv_bfloat16* __restrict__ A, const __nv_bfloat16* __restrict__ B,
    const float* __restrict__ bias, float* __restrict__ Yf,
    __nv_bfloat16* __restrict__ Ys)
{
    extern __shared__ char smem[];
    const uint32_t sb = smem_u32(smem);
    const int tid  = threadIdx.x;
    const int wid  = tid >> 5;
    const int lane = tid & 31;
    const int wm   = wid & 1;
    const int wn   = wid >> 1;
    const int row0 = blockIdx.y << 7;
    const int col0 = blockIdx.x << 7;

    const int g  = lane >> 3;
    const int r8 = lane & 7;
    const uint32_t aconst = (uint32_t)((wm * 8 + (g & 1)) * 512 + (g >> 1) * 128 + r8 * 16);
    const uint32_t bconst = (uint32_t)(wn * 4 * 512 + (g & 1) * 128 + r8 * 16);

    float acc[4][4][4];
    #pragma unroll
    for (int mt = 0; mt < 4; mt++)
        #pragma unroll
        for (int nt = 0; nt < 4; nt++)
            acc[mt][nt][0] = acc[mt][nt][1] = acc[mt][nt][2] = acc[mt][nt][3] = 0.f;

    load_tile_pair(A, B, row0, col0, 0, sb, sb + 8192, tid);
    asm volatile("cp.async.commit_group;" ::: "memory");
    load_tile_pair(A, B, row0, col0, 32, sb + STAGE_BYTES, sb + STAGE_BYTES + 8192, tid);
    asm volatile("cp.async.commit_group;" ::: "memory");

    int buf = 0;
    for (int t = 0; t < NTILES; t++) {
        asm volatile("cp.async.wait_group 1;" ::: "memory");
        __syncthreads();

        int nbuf = buf + 1; if (nbuf == 3) nbuf = 0;
        int lbuf = nbuf + 1; if (lbuf == 3) lbuf = 0;
        if (t + 2 < NTILES) {
            uint32_t ls = sb + (uint32_t)lbuf * STAGE_BYTES;
            load_tile_pair(A, B, row0, col0, (t + 2) * 32, ls, ls + 8192, tid);
        }
        asm volatile("cp.async.commit_group;" ::: "memory");

        const uint32_t Ab = sb + (uint32_t)buf * STAGE_BYTES;
        const uint32_t Bb = Ab + 8192;
        #pragma unroll
        for (int kt = 0; kt < 2; kt++) {
            uint32_t af[4][4], bfr[4][2];
            #pragma unroll
            for (int mt = 0; mt < 4; mt++)
                ldsm4(af[mt], Ab + aconst + (uint32_t)(mt * 1024 + kt * 256));
            #pragma unroll
            for (int nt = 0; nt < 4; nt++)
                ldsm2(bfr[nt], Bb + bconst + (uint32_t)(nt * 512 + kt * 256));
            #pragma unroll
            for (int mt = 0; mt < 4; mt++)
                #pragma unroll
                for (int nt = 0; nt < 4; nt++)
                    mma16816(acc[mt][nt], af[mt], bfr[nt]);
        }
        buf = nbuf;
    }

    const int mbase = row0 + wm * 64 + (lane >> 2);
    const int nbase = col0 + wn * 32 + (lane & 3) * 2;
    #pragma unroll
    for (int mt = 0; mt < 4; mt++) {
        #pragma unroll
        for (int nt = 0; nt < 4; nt++) {
            int m = mbase + mt * 16;
            int n = nbase + nt * 8;
            float2 b2 = *(const float2*)&bias[n];
            float y0 = acc[mt][nt][0] + b2.x, y1 = acc[mt][nt][1] + b2.y;
            float y2 = acc[mt][nt][2] + b2.x, y3 = acc[mt][nt][3] + b2.y;
            if (SPLIT) {
                split2(y0, y1, Ys + (size_t)m * KEFF + n);
                split2(y2, y3, Ys + (size_t)(m + 8) * KEFF + n);
            } else {
                *(float2*)&Yf[(size_t)m * FDIM + n]       = make_float2(y0, y1);
                *(float2*)&Yf[(size_t)(m + 8) * FDIM + n] = make_float2(y2, y3);
            }
        }
    }
}

// stage 1: x-split @ {wq,wk,wv} -> split(q/k/v).  grid.z = 3
__global__ __launch_bounds__(256) void gemm_s1_kernel(
    const float* b0, const float* b1, const float* b2)
{
    const int z = blockIdx.z;
    const __nv_bfloat16* W = g_wb + (size_t)z * WSZ;
    const float* bias = (z == 0) ? b0 : (z == 1) ? b1 : b2;
    __nv_bfloat16* Ys = (z == 0) ? g_abq : (z == 1) ? g_abk : g_abv;
    gemm_core<true>(g_ab, W, bias, nullptr, Ys);
}

// stage 2: split(q/k/v) @ {wiq,wik,wiv} -> fp32 q2/k2/v2.  grid.z = 3
__global__ __launch_bounds__(256) void gemm_s2_kernel(
    const float* b0, const float* b1, const float* b2)
{
    const int z = blockIdx.z;
    const __nv_bfloat16* A = (z == 0) ? g_abq : (z == 1) ? g_abk : g_abv;
    const __nv_bfloat16* W = g_wb + (size_t)(3 + z) * WSZ;
    const float* bias = (z == 0) ? b0 : (z == 1) ? b1 : b2;
    float* Yf = (z == 0) ? g_q2 : (z == 1) ? g_k2 : g_v2;
    gemm_core<false>(A, W, bias, Yf, nullptr);
}

// final: split(att) @ wo -> out fp32
__global__ __launch_bounds__(256) void gemm_final_kernel(const float* bias, float* Y) {
    gemm_core<false>(g_abatt, g_wb + (size_t)6 * WSZ, bias, Y, nullptr);
}

// ---------------- sparse gather attention (split-output epilogue) ----------------
__global__ __launch_bounds__(512) void attn_sparse_kernel(const float* __restrict__ etw)
{
    __shared__ float q_s[FDIM];
    __shared__ int   nbr_s[MAXDEG];
    __shared__ float sc_s[16][MAXDEG];
    __shared__ float wsh_s[8];

    const int n    = blockIdx.x;
    const int tid  = threadIdx.x;
    const int hh   = tid >> 5;
    const int lane = tid & 31;

    if (tid < 4) wsh_s[tid + 1] = log1pf(expf(etw[tid]));
    ((float2*)q_s)[tid] = ((const float2*)(g_q2 + (size_t)n * FDIM))[tid];
    const int deg = g_deg[n];
    for (int j = tid; j < deg; j += 512) nbr_s[j] = g_adj[n * MAXDEG + j];
    __syncthreads();

    float4 qv[16];
    #pragma unroll
    for (int i = 0; i < 16; i++) qv[i] = *(const float4*)&q_s[hh * HD + i * 4];

    float mx = -1e30f;
    for (int base = 0; base < deg; base += 32) {
        int   j = base + lane;
        float s = -1e30f;
        if (j < deg) {
            int pk   = nbr_s[j];
            int m    = pk & 0xFFFFF;
            int code = pk >> 20;
            const float4* kp = (const float4*)(g_k2 + (size_t)m * FDIM + hh * HD);
            float a0 = 0.f, a1 = 0.f, a2 = 0.f, a3 = 0.f;
            #pragma unroll
            for (int i = 0; i < 16; i += 4) {
                float4 k0 = kp[i + 0], k1 = kp[i + 1], k2 = kp[i + 2], k3 = kp[i + 3];
                a0 = fmaf(qv[i+0].x, k0.x, a0); a0 = fmaf(qv[i+0].y, k0.y, a0);
                a0 = fmaf(qv[i+0].z, k0.z, a0); a0 = fmaf(qv[i+0].w, k0.w, a0);
                a1 = fmaf(qv[i+1].x, k1.x, a1); a1 = fmaf(qv[i+1].y, k1.y, a1);
                a1 = fmaf(qv[i+1].z, k1.z, a1); a1 = fmaf(qv[i+1].w, k1.w, a1);
                a2 = fmaf(qv[i+2].x, k2.x, a2); a2 = fmaf(qv[i+2].y, k2.y, a2);
                a2 = fmaf(qv[i+2].z, k2.z, a2); a2 = fmaf(qv[i+2].w, k2.w, a2);
                a3 = fmaf(qv[i+3].x, k3.x, a3); a3 = fmaf(qv[i+3].y, k3.y, a3);
                a3 = fmaf(qv[i+3].z, k3.z, a3); a3 = fmaf(qv[i+3].w, k3.w, a3);
            }
            float acc = (a0 + a1) + (a2 + a3);
            s = fmaf(acc, 0.125f, wsh_s[code]);
            sc_s[hh][j] = s;
        }
        mx = fmaxf(mx, s);
    }
    #pragma unroll
    for (int off = 16; off; off >>= 1)
        mx = fmaxf(mx, __shfl_xor_sync(0xffffffffu, mx, off));
    __syncwarp();

    float sum = 0.f;
    for (int j = lane; j < deg; j += 32) {
        float p = __expf(sc_s[hh][j] - mx);
        sc_s[hh][j] = p;
        sum += p;
    }
    #pragma unroll
    for (int off = 16; off; off >>= 1)
        sum += __shfl_xor_sync(0xffffffffu, sum, off);
    const float inv = 1.f / sum;
    __syncwarp();

    const int dof = hh * HD + lane * 2;
    float o0 = 0.f, o1 = 0.f;
    #pragma unroll 4
    for (int j = 0; j < deg; j++) {
        int   m = nbr_s[j] & 0xFFFFF;
        float p = sc_s[hh][j];
        float2 vv = *(const float2*)(g_v2 + (size_t)m * FDIM + dof);
        o0 = fmaf(p, vv.x, o0);
        o1 = fmaf(p, vv.y, o1);
    }
    split2(o0 * inv, o1 * inv, g_abatt + (size_t)n * KEFF + dof);
}

// ---------------- launch ----------------
extern "C" void kernel_launch(void* const* d_in, const int* in_sizes, int n_in,
                              void* d_out, int out_size) {
    const float* x   = (const float*)d_in[0];
    const int*   ei  = (const int*)d_in[1];
    const int*   et  = (const int*)d_in[2];
    const float* etw = (const float*)d_in[3];
    WPtrs wp;
    wp.p[0] = (const float*)d_in[4];   // wq
    wp.p[1] = (const float*)d_in[6];   // wk
    wp.p[2] = (const float*)d_in[8];   // wv
    wp.p[3] = (const float*)d_in[10];  // wiq
    wp.p[4] = (const float*)d_in[12];  // wik
    wp.p[5] = (const float*)d_in[14];  // wiv
    wp.p[6] = (const float*)d_in[16];  // wo
    const float* bq  = (const float*)d_in[5];
    const float* bk  = (const float*)d_in[7];
    const float* bv  = (const float*)d_in[9];
    const float* biq = (const float*)d_in[11];
    const float* bik = (const float*)d_in[13];
    const float* biv = (const float*)d_in[15];
    const float* bo  = (const float*)d_in[17];
    float* out = (float*)d_out;

    __nv_bfloat16* pab;
    cudaGetSymbolAddress((void**)&pab, g_ab);

    cudaFuncSetAttribute(gemm_s1_kernel,    cudaFuncAttributeMaxDynamicSharedMemorySize, GEMM_SMEM);
    cudaFuncSetAttribute(gemm_s2_kernel,    cudaFuncAttributeMaxDynamicSharedMemorySize, GEMM_SMEM);
    cudaFuncSetAttribute(gemm_final_kernel, cudaFuncAttributeMaxDynamicSharedMemorySize, GEMM_SMEM);

    // sparse mask / adjacency
    zero_cnt_kernel<<<(NN + 255) / 256, 256>>>();
    scatter2_kernel<<<(EE + 255) / 256, 256>>>(ei, et);
    csr2_kernel<<<NN, 256>>>();

    // weight splits (all 7 in one launch)
    conv_w_all_kernel<<<dim3(FDIM * FDIM / 4 / 256, 7), 256>>>(wp);

    // activation split of x
    conv_act_kernel<<<NN * FDIM / 4 / 256, 256>>>(x, pab);

    dim3 g1(FDIM / 128, NN / 128, 3);   // (8, 24, 3) = 576 CTAs
    gemm_s1_kernel<<<g1, 256, GEMM_SMEM>>>(bq, bk, bv);
    gemm_s2_kernel<<<g1, 256, GEMM_SMEM>>>(biq, bik, biv);

    attn_sparse_kernel<<<NN, 512>>>(etw);

    dim3 gf(FDIM / 128, NN / 128);
    gemm_final_kernel<<<gf, 256, GEMM_SMEM>>>(bo, out);
}

// round 8
// speedup vs baseline: 3.2004x; 1.0350x over previous
#include <cuda_runtime.h>
#include <cuda_bf16.h>
#include <math.h>
#include <stdint.h>

#define NN     3072
#define EE     98304
#define FDIM   1024
#define HD     64
#define MAXDEG 256
#define KEFF   3072          // 3*FDIM: [hi|hi|lo] x [hi|lo|hi]
#define NTILES (KEFF / 32)   // 96 BK32 tiles
#define WSZ    ((size_t)FDIM * KEFF)

// ---------------- scratch (static device arrays; no allocation) ----------------
__device__ int   g_cnt[NN];
__device__ int   g_ecol[NN * MAXDEG];
__device__ int   g_eeid[NN * MAXDEG];
__device__ int   g_adj[NN * MAXDEG];
__device__ int   g_deg[NN];
__device__ float g_q2[NN * FDIM];
__device__ float g_k2[NN * FDIM];
__device__ float g_v2[NN * FDIM];
__device__ float g_wf[3 * FDIM * FDIM];       // fused weights Wi*W (fp32)
__device__ float g_bf[3 * FDIM];              // fused biases
__device__ float g_zero[FDIM];                // zero bias (static zero-init)
__device__ __nv_bfloat16 g_ab   [NN * KEFF];  // act split of x
__device__ __nv_bfloat16 g_abatt[NN * KEFF];  // act split of attn output
__device__ __nv_bfloat16 g_wia[3 * FDIM * KEFF];  // act split of Wiq/Wik/Wiv
__device__ __nv_bfloat16 g_wtb[3 * WSZ];          // weight split of Wq^T/Wk^T/Wv^T
__device__ __nv_bfloat16 g_wb [4 * WSZ];          // weight splits: Wf0..2, wo

// ---------------- PTX helpers ----------------
__device__ __forceinline__ uint32_t smem_u32(const void* p) {
    uint32_t a;
    asm("{ .reg .u64 t; cvta.to.shared.u64 t, %1; cvt.u32.u64 %0, t; }" : "=r"(a) : "l"(p));
    return a;
}
__device__ __forceinline__ void cp16(uint32_t dst, const void* src) {
    asm volatile("cp.async.cg.shared.global [%0], [%1], 16;" :: "r"(dst), "l"(src));
}
__device__ __forceinline__ void ldsm4(uint32_t* r, uint32_t a) {
    asm volatile("ldmatrix.sync.aligned.m8n8.x4.shared.b16 {%0,%1,%2,%3}, [%4];"
                 : "=r"(r[0]), "=r"(r[1]), "=r"(r[2]), "=r"(r[3]) : "r"(a));
}
__device__ __forceinline__ void ldsm2(uint32_t* r, uint32_t a) {
    asm volatile("ldmatrix.sync.aligned.m8n8.x2.shared.b16 {%0,%1}, [%2];"
                 : "=r"(r[0]), "=r"(r[1]) : "r"(a));
}
__device__ __forceinline__ void mma16816(float* c, const uint32_t* a, const uint32_t* b) {
    asm volatile(
        "mma.sync.aligned.m16n8k16.row.col.f32.bf16.bf16.f32 "
        "{%0,%1,%2,%3}, {%4,%5,%6,%7}, {%8,%9}, {%0,%1,%2,%3};"
        : "+f"(c[0]), "+f"(c[1]), "+f"(c[2]), "+f"(c[3])
        : "r"(a[0]), "r"(a[1]), "r"(a[2]), "r"(a[3]), "r"(b[0]), "r"(b[1]));
}

// ---------------- sparse mask / adjacency build ----------------
__global__ void zero_cnt_kernel() {
    int i = blockIdx.x * blockDim.x + threadIdx.x;
    if (i < NN) g_cnt[i] = 0;
}

__global__ void scatter2_kernel(const int* __restrict__ ei, const int* __restrict__ et) {
    int e = blockIdx.x * blockDim.x + threadIdx.x;
    if (e < EE) {
        int s = ei[e], d = ei[EE + e];
        int pos = atomicAdd(&g_cnt[s], 1);
        if (pos < MAXDEG) {
            g_ecol[s * MAXDEG + pos] = d | (et[e] << 20);
            g_eeid[s * MAXDEG + pos] = e;
        }
    }
}

__global__ __launch_bounds__(256) void csr2_kernel() {
    const int n   = blockIdx.x;
    const int tid = threadIdx.x;
    __shared__ int scol[MAXDEG], seid[MAXDEG];
    __shared__ int outc, sflag;
    if (tid == 0) { outc = 0; sflag = 0; }
    int cnt = g_cnt[n];
    if (cnt > MAXDEG) cnt = MAXDEG;
    if (tid < cnt) {
        scol[tid] = g_ecol[n * MAXDEG + tid];
        seid[tid] = g_eeid[n * MAXDEG + tid];
    }
    __syncthreads();
    if (tid < cnt) {
        int cj = scol[tid] & 0xFFFFF;
        int ej = seid[tid];
        bool win = true;
        for (int i = 0; i < cnt; i++)
            if ((scol[i] & 0xFFFFF) == cj && seid[i] > ej) { win = false; break; }
        if (win) {
            int pos = atomicAdd(&outc, 1);
            g_adj[n * MAXDEG + pos] = scol[tid];
            if (cj == n) sflag = 1;
        }
    }
    __syncthreads();
    if (tid == 0) {
        int d = outc;
        if (!sflag && d < MAXDEG) { g_adj[n * MAXDEG + d] = n | (4 << 20); d++; }
        g_deg[n] = d;
    }
}

// ---------------- fp32 -> bf16 hi/lo splits ----------------
// act layout per row: [hi | hi | lo]; weight layout per row: [hi | lo | hi].
__device__ __forceinline__ void split2(float y0, float y1, __nv_bfloat16* p) {
    __nv_bfloat162 h, l;
    h.x = __float2bfloat16(y0); h.y = __float2bfloat16(y1);
    l.x = __float2bfloat16(y0 - __bfloat162float(h.x));
    l.y = __float2bfloat16(y1 - __bfloat162float(h.y));
    *(__nv_bfloat162*)(p)        = h;
    *(__nv_bfloat162*)(p + 1024) = h;
    *(__nv_bfloat162*)(p + 2048) = l;
}

__global__ __launch_bounds__(256) void conv_act_kernel(const float* __restrict__ X,
                                                       __nv_bfloat16* __restrict__ A,
                                                       int n4) {
    int i = blockIdx.x * 256 + threadIdx.x;
    if (i >= n4) return;
    float4 v = ((const float4*)X)[i];
    int m = i >> 8;
    int c = (i & 255) << 2;
    __nv_bfloat16* row = A + (size_t)m * KEFF + c;
    split2(v.x, v.y, row);
    split2(v.z, v.w, row + 2);
}

struct WP3 { const float* p[3]; };
struct WP4 { const float* p[4]; };

// act-layout split of the inner weights Wiq/Wik/Wiv (A operand of fusion GEMM)
__global__ __launch_bounds__(256) void conv_wia_kernel(WP3 wp) {
    const int w = blockIdx.y;
    int i = blockIdx.x * 256 + threadIdx.x;     // over FDIM*FDIM/4
    if (i >= FDIM * FDIM / 4) return;
    float4 v = ((const float4*)wp.p[w])[i];
    int m = i >> 8;
    int c = (i & 255) << 2;
    __nv_bfloat16* row = g_wia + (size_t)w * FDIM * KEFF + (size_t)m * KEFF + c;
    split2(v.x, v.y, row);
    split2(v.z, v.w, row + 2);
}

// weight-layout split of W^T (B operand of fusion GEMM): out[n, k] from W[k, n]
__global__ __launch_bounds__(256) void conv_wt_kernel(WP3 wp) {
    const int w = blockIdx.z;
    const float* W = wp.p[w];
    __shared__ float t[32][33];
    const int tx = threadIdx.x & 31;
    const int ty = threadIdx.x >> 5;
    const int n0 = blockIdx.x * 32;
    const int k0 = blockIdx.y * 32;
    #pragma unroll
    for (int r = ty; r < 32; r += 8)
        t[r][tx] = W[(size_t)(k0 + r) * FDIM + n0 + tx];
    __syncthreads();
    __nv_bfloat16* B = g_wtb + (size_t)w * WSZ;
    #pragma unroll
    for (int rr = ty; rr < 32; rr += 8) {
        float v = t[tx][rr];                    // = W[k0+tx][n0+rr]
        __nv_bfloat16 h = __float2bfloat16(v);
        __nv_bfloat16 l = __float2bfloat16(v - __bfloat162float(h));
        __nv_bfloat16* row = B + (size_t)(n0 + rr) * KEFF + k0 + tx;
        row[0]    = h;      // [hi | lo | hi]
        row[1024] = l;
        row[2048] = h;
    }
}

// weight-layout split of Wf0..2 (device fp32) and wo
__global__ __launch_bounds__(256) void conv_w_all_kernel(WP4 wp) {
    const int w = blockIdx.y;
    const float* W = wp.p[w];
    __nv_bfloat16* B = g_wb + (size_t)w * WSZ;
    int i = blockIdx.x * 256 + threadIdx.x;
    if (i >= FDIM * FDIM / 4) return;
    float4 v = ((const float4*)W)[i];
    int n = i >> 8;
    int c = (i & 255) << 2;
    __nv_bfloat162 h01, h23, l01, l23;
    h01.x = __float2bfloat16(v.x); h01.y = __float2bfloat16(v.y);
    h23.x = __float2bfloat16(v.z); h23.y = __float2bfloat16(v.w);
    l01.x = __float2bfloat16(v.x - __bfloat162float(h01.x));
    l01.y = __float2bfloat16(v.y - __bfloat162float(h01.y));
    l23.x = __float2bfloat16(v.z - __bfloat162float(h23.x));
    l23.y = __float2bfloat16(v.w - __bfloat162float(h23.y));
    __nv_bfloat16* row = B + (size_t)n * KEFF + c;
    *(__nv_bfloat162*)(row)        = h01; *(__nv_bfloat162*)(row + 2)    = h23;
    *(__nv_bfloat162*)(row + 1024) = l01; *(__nv_bfloat162*)(row + 1026) = l23;
    *(__nv_bfloat162*)(row + 2048) = h01; *(__nv_bfloat162*)(row + 2050) = h23;
}

// fused bias: bf[z][n] = bi[z][n] + sum_k Wi[z][n,k] * b[z][k]
__global__ __launch_bounds__(256) void bias_fuse_kernel(WP3 wi, WP3 bin, WP3 bout) {
    const int z = blockIdx.y;
    const int n = blockIdx.x * 256 + threadIdx.x;
    const float* W = wi.p[z] + (size_t)n * FDIM;
    const float* b = bin.p[z];
    float s = 0.f;
    #pragma unroll 8
    for (int k = 0; k < FDIM; k++) s = fmaf(W[k], b[k], s);
    g_bf[z * FDIM + n] = s + bout.p[z][n];
}

// ---------------- mma.sync bf16 GEMM core ----------------
#define STAGE_BYTES 16384
#define GEMM_SMEM   (3 * STAGE_BYTES)

__device__ __forceinline__ void load_tile_pair(
    const __nv_bfloat16* Abase, const __nv_bfloat16* Bbase,
    int row0, int col0, int k0, uint32_t sA, uint32_t sB, int tid)
{
    #pragma unroll
    for (int i = 0; i < 2; i++) {
        int c   = tid + i * 256;
        int row = c >> 2;
        int kc  = c & 3;
        uint32_t soff = (uint32_t)(((row >> 3) * 4 + kc) * 128 + (row & 7) * 16);
        cp16(sA + soff, Abase + (size_t)(row0 + row) * KEFF + k0 + kc * 8);
        cp16(sB + soff, Bbase + (size_t)(col0 + row) * KEFF + k0 + kc * 8);
    }
}

template<bool SPLIT>
__device__ __forceinline__ void gemm_core(
    const __nv_bfloat16* __restrict__ A, const __nv_bfloat16* __restrict__ B,
    const float* __restrict__ bias, float* __restrict__ Yf,
    __nv_bfloat16* __restrict__ Ys)
{
    extern __shared__ char smem[];
    const uint32_t sb = smem_u32(smem);
    const int tid  = threadIdx.x;
    const int wid  = tid >> 5;
    const int lane = tid & 31;
    const int wm   = wid & 1;
    const int wn   = wid >> 1;
    const int row0 = blockIdx.y << 7;
    const int col0 = blockIdx.x << 7;

    const int g  = lane >> 3;
    const int r8 = lane & 7;
    const uint32_t aconst = (uint32_t)((wm * 8 + (g & 1)) * 512 + (g >> 1) * 128 + r8 * 16);
    const uint32_t bconst = (uint32_t)(wn * 4 * 512 + (g & 1) * 128 + r8 * 16);

    float acc[4][4][4];
    #pragma unroll
    for (int mt = 0; mt < 4; mt++)
        #pragma unroll
        for (int nt = 0; nt < 4; nt++)
            acc[mt][nt][0] = acc[mt][nt][1] = acc[mt][nt][2] = acc[mt][nt][3] = 0.f;

    load_tile_pair(A, B, row0, col0, 0, sb, sb + 8192, tid);
    asm volatile("cp.async.commit_group;" ::: "memory");
    load_tile_pair(A, B, row0, col0, 32, sb + STAGE_BYTES, sb + STAGE_BYTES + 8192, tid);
    asm volatile("cp.async.commit_group;" ::: "memory");

    int buf = 0;
    for (int t = 0; t < NTILES; t++) {
        asm volatile("cp.async.wait_group 1;" ::: "memory");
        __syncthreads();

        int nbuf = buf + 1; if (nbuf == 3) nbuf = 0;
        int lbuf = nbuf + 1; if (lbuf == 3) lbuf = 0;
        if (t + 2 < NTILES) {
            uint32_t ls = sb + (uint32_t)lbuf * STAGE_BYTES;
            load_tile_pair(A, B, row0, col0, (t + 2) * 32, ls, ls + 8192, tid);
        }
        asm volatile("cp.async.commit_group;" ::: "memory");

        const uint32_t Ab = sb + (uint32_t)buf * STAGE_BYTES;
        const uint32_t Bb = Ab + 8192;
        #pragma unroll
        for (int kt = 0; kt < 2; kt++) {
            uint32_t af[4][4], bfr[4][2];
            #pragma unroll
            for (int mt = 0; mt < 4; mt++)
                ldsm4(af[mt], Ab + aconst + (uint32_t)(mt * 1024 + kt * 256));
            #pragma unroll
            for (int nt = 0; nt < 4; nt++)
                ldsm2(bfr[nt], Bb + bconst + (uint32_t)(nt * 512 + kt * 256));
            #pragma unroll
            for (int mt = 0; mt < 4; mt++)
                #pragma unroll
                for (int nt = 0; nt < 4; nt++)
                    mma16816(acc[mt][nt], af[mt], bfr[nt]);
        }
        buf = nbuf;
    }

    const int mbase = row0 + wm * 64 + (lane >> 2);
    const int nbase = col0 + wn * 32 + (lane & 3) * 2;
    #pragma unroll
    for (int mt = 0; mt < 4; mt++) {
        #pragma unroll
        for (int nt = 0; nt < 4; nt++) {
            int m = mbase + mt * 16;
            int n = nbase + nt * 8;
            float2 b2 = *(const float2*)&bias[n];
            float y0 = acc[mt][nt][0] + b2.x, y1 = acc[mt][nt][1] + b2.y;
            float y2 = acc[mt][nt][2] + b2.x, y3 = acc[mt][nt][3] + b2.y;
            if (SPLIT) {
                split2(y0, y1, Ys + (size_t)m * KEFF + n);
                split2(y2, y3, Ys + (size_t)(m + 8) * KEFF + n);
            } else {
                *(float2*)&Yf[(size_t)m * FDIM + n]       = make_float2(y0, y1);
                *(float2*)&Yf[(size_t)(m + 8) * FDIM + n] = make_float2(y2, y3);
            }
        }
    }
}

// weight fusion: Wf[z] = Wi[z] @ W[z]  (M=1024), grid (8, 8, 3)
__global__ __launch_bounds__(256) void gemm_fuse_kernel() {
    const int z = blockIdx.z;
    gemm_core<false>(g_wia + (size_t)z * FDIM * KEFF,
                     g_wtb + (size_t)z * WSZ,
                     g_zero,
                     g_wf + (size_t)z * FDIM * FDIM, nullptr);
}

// main: q2/k2/v2 = x-split @ Wf[z]-split + bf[z]  (M=3072), grid (8, 24, 3)
__global__ __launch_bounds__(256) void gemm_main_kernel() {
    const int z = blockIdx.z;
    float* Yf = (z == 0) ? g_q2 : (z == 1) ? g_k2 : g_v2;
    gemm_core<false>(g_ab, g_wb + (size_t)z * WSZ, g_bf + z * FDIM, Yf, nullptr);
}

// final: split(att) @ wo + bo -> out
__global__ __launch_bounds__(256) void gemm_final_kernel(const float* bias, float* Y) {
    gemm_core<false>(g_abatt, g_wb + (size_t)3 * WSZ, bias, Y, nullptr);
}

// ---------------- sparse gather attention (split-output epilogue) ----------------
__global__ __launch_bounds__(512) void attn_sparse_kernel(const float* __restrict__ etw)
{
    __shared__ float q_s[FDIM];
    __shared__ int   nbr_s[MAXDEG];
    __shared__ float sc_s[16][MAXDEG];
    __shared__ float wsh_s[8];

    const int n    = blockIdx.x;
    const int tid  = threadIdx.x;
    const int hh   = tid >> 5;
    const int lane = tid & 31;

    if (tid < 4) wsh_s[tid + 1] = log1pf(expf(etw[tid]));
    ((float2*)q_s)[tid] = ((const float2*)(g_q2 + (size_t)n * FDIM))[tid];
    const int deg = g_deg[n];
    for (int j = tid; j < deg; j += 512) nbr_s[j] = g_adj[n * MAXDEG + j];
    __syncthreads();

    float4 qv[16];
    #pragma unroll
    for (int i = 0; i < 16; i++) qv[i] = *(const float4*)&q_s[hh * HD + i * 4];

    float mx = -1e30f;
    for (int base = 0; base < deg; base += 32) {
        int   j = base + lane;
        float s = -1e30f;
        if (j < deg) {
            int pk   = nbr_s[j];
            int m    = pk & 0xFFFFF;
            int code = pk >> 20;
            const float4* kp = (const float4*)(g_k2 + (size_t)m * FDIM + hh * HD);
            float a0 = 0.f, a1 = 0.f, a2 = 0.f, a3 = 0.f;
            #pragma unroll
            for (int i = 0; i < 16; i += 4) {
                float4 k0 = kp[i + 0], k1 = kp[i + 1], k2 = kp[i + 2], k3 = kp[i + 3];
                a0 = fmaf(qv[i+0].x, k0.x, a0); a0 = fmaf(qv[i+0].y, k0.y, a0);
                a0 = fmaf(qv[i+0].z, k0.z, a0); a0 = fmaf(qv[i+0].w, k0.w, a0);
                a1 = fmaf(qv[i+1].x, k1.x, a1); a1 = fmaf(qv[i+1].y, k1.y, a1);
                a1 = fmaf(qv[i+1].z, k1.z, a1); a1 = fmaf(qv[i+1].w, k1.w, a1);
                a2 = fmaf(qv[i+2].x, k2.x, a2); a2 = fmaf(qv[i+2].y, k2.y, a2);
                a2 = fmaf(qv[i+2].z, k2.z, a2); a2 = fmaf(qv[i+2].w, k2.w, a2);
                a3 = fmaf(qv[i+3].x, k3.x, a3); a3 = fmaf(qv[i+3].y, k3.y, a3);
                a3 = fmaf(qv[i+3].z, k3.z, a3); a3 = fmaf(qv[i+3].w, k3.w, a3);
            }
            float acc = (a0 + a1) + (a2 + a3);
            s = fmaf(acc, 0.125f, wsh_s[code]);
            sc_s[hh][j] = s;
        }
        mx = fmaxf(mx, s);
    }
    #pragma unroll
    for (int off = 16; off; off >>= 1)
        mx = fmaxf(mx, __shfl_xor_sync(0xffffffffu, mx, off));
    __syncwarp();

    float sum = 0.f;
    for (int j = lane; j < deg; j += 32) {
        float p = __expf(sc_s[hh][j] - mx);
        sc_s[hh][j] = p;
        sum += p;
    }
    #pragma unroll
    for (int off = 16; off; off >>= 1)
        sum += __shfl_xor_sync(0xffffffffu, sum, off);
    const float inv = 1.f / sum;
    __syncwarp();

    const int dof = hh * HD + lane * 2;
    float o0 = 0.f, o1 = 0.f;
    #pragma unroll 4
    for (int j = 0; j < deg; j++) {
        int   m = nbr_s[j] & 0xFFFFF;
        float p = sc_s[hh][j];
        float2 vv = *(const float2*)(g_v2 + (size_t)m * FDIM + dof);
        o0 = fmaf(p, vv.x, o0);
        o1 = fmaf(p, vv.y, o1);
    }
    split2(o0 * inv, o1 * inv, g_abatt + (size_t)n * KEFF + dof);
}

// ---------------- launch ----------------
extern "C" void kernel_launch(void* const* d_in, const int* in_sizes, int n_in,
                              void* d_out, int out_size) {
    const float* x   = (const float*)d_in[0];
    const int*   ei  = (const int*)d_in[1];
    const int*   et  = (const int*)d_in[2];
    const float* etw = (const float*)d_in[3];
    const float* bo  = (const float*)d_in[17];
    float* out = (float*)d_out;

    WP3 wqkv, wiqkv, bqkv, biqkv;
    wqkv.p[0]  = (const float*)d_in[4];   // wq
    wqkv.p[1]  = (const float*)d_in[6];   // wk
    wqkv.p[2]  = (const float*)d_in[8];   // wv
    bqkv.p[0]  = (const float*)d_in[5];
    bqkv.p[1]  = (const float*)d_in[7];
    bqkv.p[2]  = (const float*)d_in[9];
    wiqkv.p[0] = (const float*)d_in[10];  // wiq
    wiqkv.p[1] = (const float*)d_in[12];  // wik
    wiqkv.p[2] = (const float*)d_in[14];  // wiv
    biqkv.p[0] = (const float*)d_in[11];
    biqkv.p[1] = (const float*)d_in[13];
    biqkv.p[2] = (const float*)d_in[15];

    __nv_bfloat16* pab;
    float* pwf;
    cudaGetSymbolAddress((void**)&pab, g_ab);
    cudaGetSymbolAddress((void**)&pwf, g_wf);

    WP4 wp4;
    wp4.p[0] = pwf;
    wp4.p[1] = pwf + (size_t)FDIM * FDIM;
    wp4.p[2] = pwf + (size_t)2 * FDIM * FDIM;
    wp4.p[3] = (const float*)d_in[16];    // wo

    cudaFuncSetAttribute(gemm_fuse_kernel,  cudaFuncAttributeMaxDynamicSharedMemorySize, GEMM_SMEM);
    cudaFuncSetAttribute(gemm_main_kernel,  cudaFuncAttributeMaxDynamicSharedMemorySize, GEMM_SMEM);
    cudaFuncSetAttribute(gemm_final_kernel, cudaFuncAttributeMaxDynamicSharedMemorySize, GEMM_SMEM);

    // sparse mask / adjacency
    zero_cnt_kernel<<<(NN + 255) / 256, 256>>>();
    scatter2_kernel<<<(EE + 255) / 256, 256>>>(ei, et);
    csr2_kernel<<<NN, 256>>>();

    // weight-fusion pipeline
    conv_wia_kernel<<<dim3(FDIM * FDIM / 4 / 256, 3), 256>>>(wiqkv);
    conv_wt_kernel<<<dim3(FDIM / 32, FDIM / 32, 3), 256>>>(wqkv);
    gemm_fuse_kernel<<<dim3(FDIM / 128, FDIM / 128, 3), 256, GEMM_SMEM>>>();
    bias_fuse_kernel<<<dim3(FDIM / 256, 3), 256>>>(wiqkv, bqkv, biqkv);
    conv_w_all_kernel<<<dim3(FDIM * FDIM / 4 / 256, 4), 256>>>(wp4);

    // activation split of x
    conv_act_kernel<<<NN * FDIM / 4 / 256, 256>>>(x, pab, NN * FDIM / 4);

    // q2/k2/v2 in one launch
    gemm_main_kernel<<<dim3(FDIM / 128, NN / 128, 3), 256, GEMM_SMEM>>>();

    attn_sparse_kernel<<<NN, 512>>>(etw);

    gemm_final_kernel<<<dim3(FDIM / 128, NN / 128), 256, GEMM_SMEM>>>(bo, out);
}

// round 9
// speedup vs baseline: 4.0514x; 1.2659x over previous
#include <cuda_runtime.h>
#include <cuda_fp16.h>
#include <math.h>
#include <stdint.h>

#define NN     3072
#define EE     98304
#define FDIM   1024
#define HD     64
#define MAXDEG 256
#define K2     2048          // 2*FDIM: [hi|lo] x [hi|hi]  (fp16 2-term split)
#define NT2    (K2 / 32)     // 64 BK32 tiles
#define W2SZ   ((size_t)FDIM * K2)

// ---------------- scratch (static device arrays; no allocation) ----------------
__device__ int   g_cnt[NN];
__device__ int   g_ecol[NN * MAXDEG];
__device__ int   g_eeid[NN * MAXDEG];
__device__ int   g_adj[NN * MAXDEG];
__device__ int   g_deg[NN];
__device__ float g_q2[NN * FDIM];
__device__ float g_k2[NN * FDIM];
__device__ float g_v2[NN * FDIM];
__device__ float g_bf[3 * FDIM];              // fused biases
__device__ __half g_ab   [NN * K2];           // act split of x        [hi|lo]
__device__ __half g_abatt[NN * K2];           // act split of attn out [hi|lo]
__device__ __half g_wia[3 * W2SZ];            // act split of Wiq/Wik/Wiv
__device__ __half g_wtb[3 * W2SZ];            // weight split of Wq^T/Wk^T/Wv^T [hi|hi]
__device__ __half g_wb [4 * W2SZ];            // weight splits: Wf0..2 (from fuse), wo

// ---------------- PTX helpers ----------------
__device__ __forceinline__ uint32_t smem_u32(const void* p) {
    uint32_t a;
    asm("{ .reg .u64 t; cvta.to.shared.u64 t, %1; cvt.u32.u64 %0, t; }" : "=r"(a) : "l"(p));
    return a;
}
__device__ __forceinline__ void cp16(uint32_t dst, const void* src) {
    asm volatile("cp.async.cg.shared.global [%0], [%1], 16;" :: "r"(dst), "l"(src));
}
__device__ __forceinline__ void ldsm4(uint32_t* r, uint32_t a) {
    asm volatile("ldmatrix.sync.aligned.m8n8.x4.shared.b16 {%0,%1,%2,%3}, [%4];"
                 : "=r"(r[0]), "=r"(r[1]), "=r"(r[2]), "=r"(r[3]) : "r"(a));
}
__device__ __forceinline__ void ldsm2(uint32_t* r, uint32_t a) {
    asm volatile("ldmatrix.sync.aligned.m8n8.x2.shared.b16 {%0,%1}, [%2];"
                 : "=r"(r[0]), "=r"(r[1]) : "r"(a));
}
__device__ __forceinline__ void mma16816(float* c, const uint32_t* a, const uint32_t* b) {
    asm volatile(
        "mma.sync.aligned.m16n8k16.row.col.f32.f16.f16.f32 "
        "{%0,%1,%2,%3}, {%4,%5,%6,%7}, {%8,%9}, {%0,%1,%2,%3};"
        : "+f"(c[0]), "+f"(c[1]), "+f"(c[2]), "+f"(c[3])
        : "r"(a[0]), "r"(a[1]), "r"(a[2]), "r"(a[3]), "r"(b[0]), "r"(b[1]));
}

// ---------------- sparse mask / adjacency build ----------------
__global__ void zero_cnt_kernel() {
    int i = blockIdx.x * blockDim.x + threadIdx.x;
    if (i < NN) g_cnt[i] = 0;
}

__global__ void scatter2_kernel(const int* __restrict__ ei, const int* __restrict__ et) {
    int e = blockIdx.x * blockDim.x + threadIdx.x;
    if (e < EE) {
        int s = ei[e], d = ei[EE + e];
        int pos = atomicAdd(&g_cnt[s], 1);
        if (pos < MAXDEG) {
            g_ecol[s * MAXDEG + pos] = d | (et[e] << 20);
            g_eeid[s * MAXDEG + pos] = e;
        }
    }
}

__global__ __launch_bounds__(256) void csr2_kernel() {
    const int n   = blockIdx.x;
    const int tid = threadIdx.x;
    __shared__ int scol[MAXDEG], seid[MAXDEG];
    __shared__ int outc, sflag;
    if (tid == 0) { outc = 0; sflag = 0; }
    int cnt = g_cnt[n];
    if (cnt > MAXDEG) cnt = MAXDEG;
    if (tid < cnt) {
        scol[tid] = g_ecol[n * MAXDEG + tid];
        seid[tid] = g_eeid[n * MAXDEG + tid];
    }
    __syncthreads();
    if (tid < cnt) {
        int cj = scol[tid] & 0xFFFFF;
        int ej = seid[tid];
        bool win = true;
        for (int i = 0; i < cnt; i++)
            if ((scol[i] & 0xFFFFF) == cj && seid[i] > ej) { win = false; break; }
        if (win) {
            int pos = atomicAdd(&outc, 1);
            g_adj[n * MAXDEG + pos] = scol[tid];
            if (cj == n) sflag = 1;
        }
    }
    __syncthreads();
    if (tid == 0) {
        int d = outc;
        if (!sflag && d < MAXDEG) { g_adj[n * MAXDEG + d] = n | (4 << 20); d++; }
        g_deg[n] = d;
    }
}

// ---------------- fp32 -> fp16 2-term splits ----------------
// act layout per row: [hi | lo]; weight layout per row: [hi | hi].
__device__ __forceinline__ void split2a(float y0, float y1, __half* p) {
    __half2 h, l;
    h.x = __float2half_rn(y0); h.y = __float2half_rn(y1);
    l.x = __float2half_rn(y0 - __half2float(h.x));
    l.y = __float2half_rn(y1 - __half2float(h.y));
    *(__half2*)(p)        = h;
    *(__half2*)(p + 1024) = l;
}

__global__ __launch_bounds__(256) void conv_act_kernel(const float* __restrict__ X,
                                                       __half* __restrict__ A, int n4) {
    int i = blockIdx.x * 256 + threadIdx.x;
    if (i >= n4) return;
    float4 v = ((const float4*)X)[i];
    int m = i >> 8;
    int c = (i & 255) << 2;
    __half* row = A + (size_t)m * K2 + c;
    split2a(v.x, v.y, row);
    split2a(v.z, v.w, row + 2);
}

struct WP3 { const float* p[3]; };

// act-layout split of the inner weights Wiq/Wik/Wiv (A operand of fusion GEMM)
__global__ __launch_bounds__(256) void conv_wia_kernel(WP3 wp) {
    const int w = blockIdx.y;
    int i = blockIdx.x * 256 + threadIdx.x;
    if (i >= FDIM * FDIM / 4) return;
    float4 v = ((const float4*)wp.p[w])[i];
    int m = i >> 8;
    int c = (i & 255) << 2;
    __half* row = g_wia + (size_t)w * W2SZ + (size_t)m * K2 + c;
    split2a(v.x, v.y, row);
    split2a(v.z, v.w, row + 2);
}

// weight-layout split of W^T (B operand of fusion GEMM): out[n,k] = hi(W[k,n]) dup
__global__ __launch_bounds__(256) void conv_wt_kernel(WP3 wp) {
    const int w = blockIdx.z;
    const float* W = wp.p[w];
    __shared__ float t[32][33];
    const int tx = threadIdx.x & 31;
    const int ty = threadIdx.x >> 5;
    const int n0 = blockIdx.x * 32;
    const int k0 = blockIdx.y * 32;
    #pragma unroll
    for (int r = ty; r < 32; r += 8)
        t[r][tx] = W[(size_t)(k0 + r) * FDIM + n0 + tx];
    __syncthreads();
    __half* B = g_wtb + (size_t)w * W2SZ;
    #pragma unroll
    for (int rr = ty; rr < 32; rr += 8) {
        __half h = __float2half_rn(t[tx][rr]);    // = W[k0+tx][n0+rr]
        __half* row = B + (size_t)(n0 + rr) * K2 + k0 + tx;
        row[0]    = h;
        row[1024] = h;
    }
}

// weight-layout split (duplicate hi) of wo
__global__ __launch_bounds__(256) void conv_wo_kernel(const float* __restrict__ W) {
    int i = blockIdx.x * 256 + threadIdx.x;
    if (i >= FDIM * FDIM / 4) return;
    float4 v = ((const float4*)W)[i];
    int n = i >> 8;
    int c = (i & 255) << 2;
    __half2 h01, h23;
    h01.x = __float2half_rn(v.x); h01.y = __float2half_rn(v.y);
    h23.x = __float2half_rn(v.z); h23.y = __float2half_rn(v.w);
    __half* row = g_wb + (size_t)3 * W2SZ + (size_t)n * K2 + c;
    *(__half2*)(row)        = h01; *(__half2*)(row + 2)    = h23;
    *(__half2*)(row + 1024) = h01; *(__half2*)(row + 1026) = h23;
}

// fused bias: bf[z][n] = bi[z][n] + sum_k Wi[z][n,k] * b[z][k]
__global__ __launch_bounds__(256) void bias_fuse_kernel(WP3 wi, WP3 bin, WP3 bout) {
    const int z = blockIdx.y;
    const int n = blockIdx.x * 256 + threadIdx.x;
    const float* W = wi.p[z] + (size_t)n * FDIM;
    const float* b = bin.p[z];
    float s = 0.f;
    #pragma unroll 8
    for (int k = 0; k < FDIM; k++) s = fmaf(W[k], b[k], s);
    g_bf[z * FDIM + n] = s + bout.p[z][n];
}

// ---------------- mma.sync fp16 GEMM core ----------------
#define STAGE_BYTES 16384
#define GEMM_SMEM   (3 * STAGE_BYTES)

__device__ __forceinline__ void load_tile_pair(
    const __half* Abase, const __half* Bbase,
    int row0, int col0, int k0, uint32_t sA, uint32_t sB, int tid)
{
    #pragma unroll
    for (int i = 0; i < 2; i++) {
        int c   = tid + i * 256;
        int row = c >> 2;
        int kc  = c & 3;
        uint32_t soff = (uint32_t)(((row >> 3) * 4 + kc) * 128 + (row & 7) * 16);
        cp16(sA + soff, Abase + (size_t)(row0 + row) * K2 + k0 + kc * 8);
        cp16(sB + soff, Bbase + (size_t)(col0 + row) * K2 + k0 + kc * 8);
    }
}

// MODE 0: fp32 out + bias.  MODE 1: weight-layout fp16 split out (no bias).
template<int MODE>
__device__ __forceinline__ void gemm_core(
    const __half* __restrict__ A, const __half* __restrict__ B,
    const float* __restrict__ bias, float* __restrict__ Yf,
    __half* __restrict__ Ys)
{
    extern __shared__ char smem[];
    const uint32_t sb = smem_u32(smem);
    const int tid  = threadIdx.x;
    const int wid  = tid >> 5;
    const int lane = tid & 31;
    const int wm   = wid & 1;
    const int wn   = wid >> 1;
    const int row0 = blockIdx.y << 7;
    const int col0 = blockIdx.x << 7;

    const int g  = lane >> 3;
    const int r8 = lane & 7;
    const uint32_t aconst = (uint32_t)((wm * 8 + (g & 1)) * 512 + (g >> 1) * 128 + r8 * 16);
    const uint32_t bconst = (uint32_t)(wn * 4 * 512 + (g & 1) * 128 + r8 * 16);

    float acc[4][4][4];
    #pragma unroll
    for (int mt = 0; mt < 4; mt++)
        #pragma unroll
        for (int nt = 0; nt < 4; nt++)
            acc[mt][nt][0] = acc[mt][nt][1] = acc[mt][nt][2] = acc[mt][nt][3] = 0.f;

    load_tile_pair(A, B, row0, col0, 0, sb, sb + 8192, tid);
    asm volatile("cp.async.commit_group;" ::: "memory");
    load_tile_pair(A, B, row0, col0, 32, sb + STAGE_BYTES, sb + STAGE_BYTES + 8192, tid);
    asm volatile("cp.async.commit_group;" ::: "memory");

    int buf = 0;
    for (int t = 0; t < NT2; t++) {
        asm volatile("cp.async.wait_group 1;" ::: "memory");
        __syncthreads();

        int nbuf = buf + 1; if (nbuf == 3) nbuf = 0;
        int lbuf = nbuf + 1; if (lbuf == 3) lbuf = 0;
        if (t + 2 < NT2) {
            uint32_t ls = sb + (uint32_t)lbuf * STAGE_BYTES;
            load_tile_pair(A, B, row0, col0, (t + 2) * 32, ls, ls + 8192, tid);
        }
        asm volatile("cp.async.commit_group;" ::: "memory");

        const uint32_t Ab = sb + (uint32_t)buf * STAGE_BYTES;
        const uint32_t Bb = Ab + 8192;
        #pragma unroll
        for (int kt = 0; kt < 2; kt++) {
            uint32_t af[4][4], bfr[4][2];
            #pragma unroll
            for (int mt = 0; mt < 4; mt++)
                ldsm4(af[mt], Ab + aconst + (uint32_t)(mt * 1024 + kt * 256));
            #pragma unroll
            for (int nt = 0; nt < 4; nt++)
                ldsm2(bfr[nt], Bb + bconst + (uint32_t)(nt * 512 + kt * 256));
            #pragma unroll
            for (int mt = 0; mt < 4; mt++)
                #pragma unroll
                for (int nt = 0; nt < 4; nt++)
                    mma16816(acc[mt][nt], af[mt], bfr[nt]);
        }
        buf = nbuf;
    }

    const int mbase = row0 + wm * 64 + (lane >> 2);
    const int nbase = col0 + wn * 32 + (lane & 3) * 2;
    #pragma unroll
    for (int mt = 0; mt < 4; mt++) {
        #pragma unroll
        for (int nt = 0; nt < 4; nt++) {
            int m = mbase + mt * 16;
            int n = nbase + nt * 8;
            if (MODE == 0) {
                float2 b2 = *(const float2*)&bias[n];
                *(float2*)&Yf[(size_t)m * FDIM + n] =
                    make_float2(acc[mt][nt][0] + b2.x, acc[mt][nt][1] + b2.y);
                *(float2*)&Yf[(size_t)(m + 8) * FDIM + n] =
                    make_float2(acc[mt][nt][2] + b2.x, acc[mt][nt][3] + b2.y);
            } else {
                __half2 h0, h1;
                h0.x = __float2half_rn(acc[mt][nt][0]);
                h0.y = __float2half_rn(acc[mt][nt][1]);
                h1.x = __float2half_rn(acc[mt][nt][2]);
                h1.y = __float2half_rn(acc[mt][nt][3]);
                __half* r0 = Ys + (size_t)m * K2 + n;
                __half* r1 = Ys + (size_t)(m + 8) * K2 + n;
                *(__half2*)(r0) = h0; *(__half2*)(r0 + 1024) = h0;
                *(__half2*)(r1) = h1; *(__half2*)(r1 + 1024) = h1;
            }
        }
    }
}

// weight fusion: Wf[z] = Wi[z] @ W[z], emitted directly as weight-layout split
__global__ __launch_bounds__(256) void gemm_fuse_kernel() {
    const int z = blockIdx.z;
    gemm_core<1>(g_wia + (size_t)z * W2SZ, g_wtb + (size_t)z * W2SZ,
                 nullptr, nullptr, g_wb + (size_t)z * W2SZ);
}

// main: q2/k2/v2 = x-split @ Wf[z]-split + bf[z]
__global__ __launch_bounds__(256) void gemm_main_kernel() {
    const int z = blockIdx.z;
    float* Yf = (z == 0) ? g_q2 : (z == 1) ? g_k2 : g_v2;
    gemm_core<0>(g_ab, g_wb + (size_t)z * W2SZ, g_bf + z * FDIM, Yf, nullptr);
}

// final: split(att) @ wo + bo -> out
__global__ __launch_bounds__(256) void gemm_final_kernel(const float* bias, float* Y) {
    gemm_core<0>(g_abatt, g_wb + (size_t)3 * W2SZ, bias, Y, nullptr);
}

// ---------------- sparse gather attention (split-output epilogue) ----------------
__global__ __launch_bounds__(512) void attn_sparse_kernel(const float* __restrict__ etw)
{
    __shared__ float q_s[FDIM];
    __shared__ int   nbr_s[MAXDEG];
    __shared__ float sc_s[16][MAXDEG];
    __shared__ float wsh_s[8];

    const int n    = blockIdx.x;
    const int tid  = threadIdx.x;
    const int hh   = tid >> 5;
    const int lane = tid & 31;

    if (tid < 4) wsh_s[tid + 1] = log1pf(expf(etw[tid]));
    ((float2*)q_s)[tid] = ((const float2*)(g_q2 + (size_t)n * FDIM))[tid];
    const int deg = g_deg[n];
    for (int j = tid; j < deg; j += 512) nbr_s[j] = g_adj[n * MAXDEG + j];
    __syncthreads();

    float4 qv[16];
    #pragma unroll
    for (int i = 0; i < 16; i++) qv[i] = *(const float4*)&q_s[hh * HD + i * 4];

    float mx = -1e30f;
    for (int base = 0; base < deg; base += 32) {
        int   j = base + lane;
        float s = -1e30f;
        if (j < deg) {
            int pk   = nbr_s[j];
            int m    = pk & 0xFFFFF;
            int code = pk >> 20;
            const float4* kp = (const float4*)(g_k2 + (size_t)m * FDIM + hh * HD);
            float a0 = 0.f, a1 = 0.f, a2 = 0.f, a3 = 0.f;
            #pragma unroll
            for (int i = 0; i < 16; i += 4) {
                float4 k0 = kp[i + 0], k1 = kp[i + 1], k2 = kp[i + 2], k3 = kp[i + 3];
                a0 = fmaf(qv[i+0].x, k0.x, a0); a0 = fmaf(qv[i+0].y, k0.y, a0);
                a0 = fmaf(qv[i+0].z, k0.z, a0); a0 = fmaf(qv[i+0].w, k0.w, a0);
                a1 = fmaf(qv[i+1].x, k1.x, a1); a1 = fmaf(qv[i+1].y, k1.y, a1);
                a1 = fmaf(qv[i+1].z, k1.z, a1); a1 = fmaf(qv[i+1].w, k1.w, a1);
                a2 = fmaf(qv[i+2].x, k2.x, a2); a2 = fmaf(qv[i+2].y, k2.y, a2);
                a2 = fmaf(qv[i+2].z, k2.z, a2); a2 = fmaf(qv[i+2].w, k2.w, a2);
                a3 = fmaf(qv[i+3].x, k3.x, a3); a3 = fmaf(qv[i+3].y, k3.y, a3);
                a3 = fmaf(qv[i+3].z, k3.z, a3); a3 = fmaf(qv[i+3].w, k3.w, a3);
            }
            float acc = (a0 + a1) + (a2 + a3);
            s = fmaf(acc, 0.125f, wsh_s[code]);
            sc_s[hh][j] = s;
        }
        mx = fmaxf(mx, s);
    }
    #pragma unroll
    for (int off = 16; off; off >>= 1)
        mx = fmaxf(mx, __shfl_xor_sync(0xffffffffu, mx, off));
    __syncwarp();

    float sum = 0.f;
    for (int j = lane; j < deg; j += 32) {
        float p = __expf(sc_s[hh][j] - mx);
        sc_s[hh][j] = p;
        sum += p;
    }
    #pragma unroll
    for (int off = 16; off; off >>= 1)
        sum += __shfl_xor_sync(0xffffffffu, sum, off);
    const float inv = 1.f / sum;
    __syncwarp();

    const int dof = hh * HD + lane * 2;
    float o0 = 0.f, o1 = 0.f;
    #pragma unroll 4
    for (int j = 0; j < deg; j++) {
        int   m = nbr_s[j] & 0xFFFFF;
        float p = sc_s[hh][j];
        float2 vv = *(const float2*)(g_v2 + (size_t)m * FDIM + dof);
        o0 = fmaf(p, vv.x, o0);
        o1 = fmaf(p, vv.y, o1);
    }
    split2a(o0 * inv, o1 * inv, g_abatt + (size_t)n * K2 + dof);
}

// ---------------- launch ----------------
extern "C" void kernel_launch(void* const* d_in, const int* in_sizes, int n_in,
                              void* d_out, int out_size) {
    const float* x   = (const float*)d_in[0];
    const int*   ei  = (const int*)d_in[1];
    const int*   et  = (const int*)d_in[2];
    const float* etw = (const float*)d_in[3];
    const float* wo  = (const float*)d_in[16];
    const float* bo  = (const float*)d_in[17];
    float* out = (float*)d_out;

    WP3 wqkv, wiqkv, bqkv, biqkv;
    wqkv.p[0]  = (const float*)d_in[4];
    wqkv.p[1]  = (const float*)d_in[6];
    wqkv.p[2]  = (const float*)d_in[8];
    bqkv.p[0]  = (const float*)d_in[5];
    bqkv.p[1]  = (const float*)d_in[7];
    bqkv.p[2]  = (const float*)d_in[9];
    wiqkv.p[0] = (const float*)d_in[10];
    wiqkv.p[1] = (const float*)d_in[12];
    wiqkv.p[2] = (const float*)d_in[14];
    biqkv.p[0] = (const float*)d_in[11];
    biqkv.p[1] = (const float*)d_in[13];
    biqkv.p[2] = (const float*)d_in[15];

    __half* pab;
    cudaGetSymbolAddress((void**)&pab, g_ab);

    cudaFuncSetAttribute(gemm_fuse_kernel,  cudaFuncAttributeMaxDynamicSharedMemorySize, GEMM_SMEM);
    cudaFuncSetAttribute(gemm_main_kernel,  cudaFuncAttributeMaxDynamicSharedMemorySize, GEMM_SMEM);
    cudaFuncSetAttribute(gemm_final_kernel, cudaFuncAttributeMaxDynamicSharedMemorySize, GEMM_SMEM);

    // sparse mask / adjacency
    zero_cnt_kernel<<<(NN + 255) / 256, 256>>>();
    scatter2_kernel<<<(EE + 255) / 256, 256>>>(ei, et);
    csr2_kernel<<<NN, 256>>>();

    // weight-fusion pipeline (fp16 splits)
    conv_wia_kernel<<<dim3(FDIM * FDIM / 4 / 256, 3), 256>>>(wiqkv);
    conv_wt_kernel<<<dim3(FDIM / 32, FDIM / 32, 3), 256>>>(wqkv);
    gemm_fuse_kernel<<<dim3(FDIM / 128, FDIM / 128, 3), 256, GEMM_SMEM>>>();
    conv_wo_kernel<<<FDIM * FDIM / 4 / 256, 256>>>(wo);
    bias_fuse_kernel<<<dim3(FDIM / 256, 3), 256>>>(wiqkv, bqkv, biqkv);

    // activation split of x
    conv_act_kernel<<<NN * FDIM / 4 / 256, 256>>>(x, pab, NN * FDIM / 4);

    // q2/k2/v2 in one launch
    gemm_main_kernel<<<dim3(FDIM / 128, NN / 128, 3), 256, GEMM_SMEM>>>();

    attn_sparse_kernel<<<NN, 512>>>(etw);

    gemm_final_kernel<<<dim3(FDIM / 128, NN / 128), 256, GEMM_SMEM>>>(bo, out);
}

// round 10
// speedup vs baseline: 5.4333x; 1.3411x over previous
#include <cuda_runtime.h>
#include <cuda_fp16.h>
#include <math.h>
#include <stdint.h>

#define NN     3072
#define EE     98304
#define FDIM   1024
#define HD     64
#define MAXDEG 256
#define KP     1024          // plain fp16 GEMM K
#define NTP    (KP / 32)     // 32 BK32 tiles
#define WPSZ   ((size_t)FDIM * KP)

// ---------------- scratch (static device arrays; no allocation) ----------------
__device__ int   g_cnt[NN];
__device__ int   g_ecol[NN * MAXDEG];
__device__ int   g_eeid[NN * MAXDEG];
__device__ int   g_adj[NN * MAXDEG];
__device__ int   g_deg[NN];
__device__ float g_q2[NN * FDIM];
__device__ float g_k2[NN * FDIM];
__device__ float g_v2[NN * FDIM];
__device__ float g_bf[3 * FDIM];              // fused biases
__device__ __half g_ab   [NN * KP];           // fp16 cast of x
__device__ __half g_abatt[NN * KP];           // fp16 cast of attn out
__device__ __half g_wia[3 * WPSZ];            // fp16 cast of Wiq/Wik/Wiv
__device__ __half g_wtb[3 * WPSZ];            // fp16 cast of Wq^T/Wk^T/Wv^T
__device__ __half g_wb [4 * WPSZ];            // fp16: Wf0..2 (from fuse), wo

// ---------------- PTX helpers ----------------
__device__ __forceinline__ uint32_t smem_u32(const void* p) {
    uint32_t a;
    asm("{ .reg .u64 t; cvta.to.shared.u64 t, %1; cvt.u32.u64 %0, t; }" : "=r"(a) : "l"(p));
    return a;
}
__device__ __forceinline__ void cp16(uint32_t dst, const void* src) {
    asm volatile("cp.async.cg.shared.global [%0], [%1], 16;" :: "r"(dst), "l"(src));
}
__device__ __forceinline__ void ldsm4(uint32_t* r, uint32_t a) {
    asm volatile("ldmatrix.sync.aligned.m8n8.x4.shared.b16 {%0,%1,%2,%3}, [%4];"
                 : "=r"(r[0]), "=r"(r[1]), "=r"(r[2]), "=r"(r[3]) : "r"(a));
}
__device__ __forceinline__ void ldsm2(uint32_t* r, uint32_t a) {
    asm volatile("ldmatrix.sync.aligned.m8n8.x2.shared.b16 {%0,%1}, [%2];"
                 : "=r"(r[0]), "=r"(r[1]) : "r"(a));
}
__device__ __forceinline__ void mma16816(float* c, const uint32_t* a, const uint32_t* b) {
    asm volatile(
        "mma.sync.aligned.m16n8k16.row.col.f32.f16.f16.f32 "
        "{%0,%1,%2,%3}, {%4,%5,%6,%7}, {%8,%9}, {%0,%1,%2,%3};"
        : "+f"(c[0]), "+f"(c[1]), "+f"(c[2]), "+f"(c[3])
        : "r"(a[0]), "r"(a[1]), "r"(a[2]), "r"(a[3]), "r"(b[0]), "r"(b[1]));
}

// ---------------- sparse mask / adjacency build ----------------
__global__ void zero_cnt_kernel() {
    int i = blockIdx.x * blockDim.x + threadIdx.x;
    if (i < NN) g_cnt[i] = 0;
}

__global__ void scatter2_kernel(const int* __restrict__ ei, const int* __restrict__ et) {
    int e = blockIdx.x * blockDim.x + threadIdx.x;
    if (e < EE) {
        int s = ei[e], d = ei[EE + e];
        int pos = atomicAdd(&g_cnt[s], 1);
        if (pos < MAXDEG) {
            g_ecol[s * MAXDEG + pos] = d | (et[e] << 20);
            g_eeid[s * MAXDEG + pos] = e;
        }
    }
}

__global__ __launch_bounds__(256) void csr2_kernel() {
    const int n   = blockIdx.x;
    const int tid = threadIdx.x;
    __shared__ int scol[MAXDEG], seid[MAXDEG];
    __shared__ int outc, sflag;
    if (tid == 0) { outc = 0; sflag = 0; }
    int cnt = g_cnt[n];
    if (cnt > MAXDEG) cnt = MAXDEG;
    if (tid < cnt) {
        scol[tid] = g_ecol[n * MAXDEG + tid];
        seid[tid] = g_eeid[n * MAXDEG + tid];
    }
    __syncthreads();
    if (tid < cnt) {
        int cj = scol[tid] & 0xFFFFF;
        int ej = seid[tid];
        bool win = true;
        for (int i = 0; i < cnt; i++)
            if ((scol[i] & 0xFFFFF) == cj && seid[i] > ej) { win = false; break; }
        if (win) {
            int pos = atomicAdd(&outc, 1);
            g_adj[n * MAXDEG + pos] = scol[tid];
            if (cj == n) sflag = 1;
        }
    }
    __syncthreads();
    if (tid == 0) {
        int d = outc;
        if (!sflag && d < MAXDEG) { g_adj[n * MAXDEG + d] = n | (4 << 20); d++; }
        g_deg[n] = d;
    }
}

// ---------------- fp32 -> fp16 casts ----------------
struct WP3 { const float* p[3]; };

__global__ __launch_bounds__(256) void conv_cast_kernel(const float* __restrict__ X,
                                                        __half* __restrict__ A, int n4) {
    int i = blockIdx.x * 256 + threadIdx.x;
    if (i >= n4) return;
    float4 v = ((const float4*)X)[i];
    __half2 h01, h23;
    h01.x = __float2half_rn(v.x); h01.y = __float2half_rn(v.y);
    h23.x = __float2half_rn(v.z); h23.y = __float2half_rn(v.w);
    *(__half2*)(A + i * 4)     = h01;
    *(__half2*)(A + i * 4 + 2) = h23;
}

__global__ __launch_bounds__(256) void conv_wia_kernel(WP3 wp) {
    const int w = blockIdx.y;
    int i = blockIdx.x * 256 + threadIdx.x;
    if (i >= FDIM * FDIM / 4) return;
    float4 v = ((const float4*)wp.p[w])[i];
    __half2 h01, h23;
    h01.x = __float2half_rn(v.x); h01.y = __float2half_rn(v.y);
    h23.x = __float2half_rn(v.z); h23.y = __float2half_rn(v.w);
    __half* A = g_wia + (size_t)w * WPSZ;
    *(__half2*)(A + i * 4)     = h01;
    *(__half2*)(A + i * 4 + 2) = h23;
}

// transpose-cast: out[n,k] = fl16(W[k,n])
__global__ __launch_bounds__(256) void conv_wt_kernel(WP3 wp) {
    const int w = blockIdx.z;
    const float* W = wp.p[w];
    __shared__ float t[32][33];
    const int tx = threadIdx.x & 31;
    const int ty = threadIdx.x >> 5;
    const int n0 = blockIdx.x * 32;
    const int k0 = blockIdx.y * 32;
    #pragma unroll
    for (int r = ty; r < 32; r += 8)
        t[r][tx] = W[(size_t)(k0 + r) * FDIM + n0 + tx];
    __syncthreads();
    __half* B = g_wtb + (size_t)w * WPSZ;
    #pragma unroll
    for (int rr = ty; rr < 32; rr += 8)
        B[(size_t)(n0 + rr) * KP + k0 + tx] = __float2half_rn(t[tx][rr]);
}

// fused bias: bf[z][n] = bi[z][n] + sum_k Wi[z][n,k] * b[z][k]
__global__ __launch_bounds__(256) void bias_fuse_kernel(WP3 wi, WP3 bin, WP3 bout) {
    const int z = blockIdx.y;
    const int n = blockIdx.x * 256 + threadIdx.x;
    const float* W = wi.p[z] + (size_t)n * FDIM;
    const float* b = bin.p[z];
    float s = 0.f;
    #pragma unroll 8
    for (int k = 0; k < FDIM; k++) s = fmaf(W[k], b[k], s);
    g_bf[z * FDIM + n] = s + bout.p[z][n];
}

// ---------------- mma.sync fp16 GEMM core ----------------
#define STAGE_BYTES 16384
#define GEMM_SMEM   (3 * STAGE_BYTES)

__device__ __forceinline__ void load_tile_pair(
    const __half* Abase, const __half* Bbase,
    int row0, int col0, int k0, uint32_t sA, uint32_t sB, int tid)
{
    #pragma unroll
    for (int i = 0; i < 2; i++) {
        int c   = tid + i * 256;
        int row = c >> 2;
        int kc  = c & 3;
        uint32_t soff = (uint32_t)(((row >> 3) * 4 + kc) * 128 + (row & 7) * 16);
        cp16(sA + soff, Abase + (size_t)(row0 + row) * KP + k0 + kc * 8);
        cp16(sB + soff, Bbase + (size_t)(col0 + row) * KP + k0 + kc * 8);
    }
}

// MODE 0: fp32 out + bias.  MODE 1: fp16 out (no bias), row stride KP.
template<int MODE>
__device__ __forceinline__ void gemm_core(
    const __half* __restrict__ A, const __half* __restrict__ B,
    const float* __restrict__ bias, float* __restrict__ Yf,
    __half* __restrict__ Ys)
{
    extern __shared__ char smem[];
    const uint32_t sb = smem_u32(smem);
    const int tid  = threadIdx.x;
    const int wid  = tid >> 5;
    const int lane = tid & 31;
    const int wm   = wid & 1;
    const int wn   = wid >> 1;
    const int row0 = blockIdx.y << 7;
    const int col0 = blockIdx.x << 7;

    const int g  = lane >> 3;
    const int r8 = lane & 7;
    const uint32_t aconst = (uint32_t)((wm * 8 + (g & 1)) * 512 + (g >> 1) * 128 + r8 * 16);
    const uint32_t bconst = (uint32_t)(wn * 4 * 512 + (g & 1) * 128 + r8 * 16);

    float acc[4][4][4];
    #pragma unroll
    for (int mt = 0; mt < 4; mt++)
        #pragma unroll
        for (int nt = 0; nt < 4; nt++)
            acc[mt][nt][0] = acc[mt][nt][1] = acc[mt][nt][2] = acc[mt][nt][3] = 0.f;

    load_tile_pair(A, B, row0, col0, 0, sb, sb + 8192, tid);
    asm volatile("cp.async.commit_group;" ::: "memory");
    load_tile_pair(A, B, row0, col0, 32, sb + STAGE_BYTES, sb + STAGE_BYTES + 8192, tid);
    asm volatile("cp.async.commit_group;" ::: "memory");

    int buf = 0;
    for (int t = 0; t < NTP; t++) {
        asm volatile("cp.async.wait_group 1;" ::: "memory");
        __syncthreads();

        int nbuf = buf + 1; if (nbuf == 3) nbuf = 0;
        int lbuf = nbuf + 1; if (lbuf == 3) lbuf = 0;
        if (t + 2 < NTP) {
            uint32_t ls = sb + (uint32_t)lbuf * STAGE_BYTES;
            load_tile_pair(A, B, row0, col0, (t + 2) * 32, ls, ls + 8192, tid);
        }
        asm volatile("cp.async.commit_group;" ::: "memory");

        const uint32_t Ab = sb + (uint32_t)buf * STAGE_BYTES;
        const uint32_t Bb = Ab + 8192;
        #pragma unroll
        for (int kt = 0; kt < 2; kt++) {
            uint32_t af[4][4], bfr[4][2];
            #pragma unroll
            for (int mt = 0; mt < 4; mt++)
                ldsm4(af[mt], Ab + aconst + (uint32_t)(mt * 1024 + kt * 256));
            #pragma unroll
            for (int nt = 0; nt < 4; nt++)
                ldsm2(bfr[nt], Bb + bconst + (uint32_t)(nt * 512 + kt * 256));
            #pragma unroll
            for (int mt = 0; mt < 4; mt++)
                #pragma unroll
                for (int nt = 0; nt < 4; nt++)
                    mma16816(acc[mt][nt], af[mt], bfr[nt]);
        }
        buf = nbuf;
    }

    const int mbase = row0 + wm * 64 + (lane >> 2);
    const int nbase = col0 + wn * 32 + (lane & 3) * 2;
    #pragma unroll
    for (int mt = 0; mt < 4; mt++) {
        #pragma unroll
        for (int nt = 0; nt < 4; nt++) {
            int m = mbase + mt * 16;
            int n = nbase + nt * 8;
            if (MODE == 0) {
                float2 b2 = *(const float2*)&bias[n];
                *(float2*)&Yf[(size_t)m * FDIM + n] =
                    make_float2(acc[mt][nt][0] + b2.x, acc[mt][nt][1] + b2.y);
                *(float2*)&Yf[(size_t)(m + 8) * FDIM + n] =
                    make_float2(acc[mt][nt][2] + b2.x, acc[mt][nt][3] + b2.y);
            } else {
                __half2 h0, h1;
                h0.x = __float2half_rn(acc[mt][nt][0]);
                h0.y = __float2half_rn(acc[mt][nt][1]);
                h1.x = __float2half_rn(acc[mt][nt][2]);
                h1.y = __float2half_rn(acc[mt][nt][3]);
                *(__half2*)(Ys + (size_t)m * KP + n)       = h0;
                *(__half2*)(Ys + (size_t)(m + 8) * KP + n) = h1;
            }
        }
    }
}

// weight fusion: Wf[z] = Wi[z] @ W[z], emitted as fp16 directly
__global__ __launch_bounds__(256) void gemm_fuse_kernel() {
    const int z = blockIdx.z;
    gemm_core<1>(g_wia + (size_t)z * WPSZ, g_wtb + (size_t)z * WPSZ,
                 nullptr, nullptr, g_wb + (size_t)z * WPSZ);
}

// main: q2/k2/v2 = fl16(x) @ Wf[z] + bf[z]
__global__ __launch_bounds__(256) void gemm_main_kernel() {
    const int z = blockIdx.z;
    float* Yf = (z == 0) ? g_q2 : (z == 1) ? g_k2 : g_v2;
    gemm_core<0>(g_ab, g_wb + (size_t)z * WPSZ, g_bf + z * FDIM, Yf, nullptr);
}

// final: fl16(att) @ wo + bo -> out
__global__ __launch_bounds__(256) void gemm_final_kernel(const float* bias, float* Y) {
    gemm_core<0>(g_abatt, g_wb + (size_t)3 * WPSZ, bias, Y, nullptr);
}

// ---------------- sparse gather attention (fp16-cast epilogue) ----------------
__global__ __launch_bounds__(512) void attn_sparse_kernel(const float* __restrict__ etw)
{
    __shared__ float q_s[FDIM];
    __shared__ int   nbr_s[MAXDEG];
    __shared__ float sc_s[16][MAXDEG];
    __shared__ float wsh_s[8];

    const int n    = blockIdx.x;
    const int tid  = threadIdx.x;
    const int hh   = tid >> 5;
    const int lane = tid & 31;

    if (tid < 4) wsh_s[tid + 1] = log1pf(expf(etw[tid]));
    ((float2*)q_s)[tid] = ((const float2*)(g_q2 + (size_t)n * FDIM))[tid];
    const int deg = g_deg[n];
    for (int j = tid; j < deg; j += 512) nbr_s[j] = g_adj[n * MAXDEG + j];
    __syncthreads();

    float4 qv[16];
    #pragma unroll
    for (int i = 0; i < 16; i++) qv[i] = *(const float4*)&q_s[hh * HD + i * 4];

    float mx = -1e30f;
    for (int base = 0; base < deg; base += 32) {
        int   j = base + lane;
        float s = -1e30f;
        if (j < deg) {
            int pk   = nbr_s[j];
            int m    = pk & 0xFFFFF;
            int code = pk >> 20;
            const float4* kp = (const float4*)(g_k2 + (size_t)m * FDIM + hh * HD);
            float a0 = 0.f, a1 = 0.f, a2 = 0.f, a3 = 0.f;
            #pragma unroll
            for (int i = 0; i < 16; i += 4) {
                float4 k0 = kp[i + 0], k1 = kp[i + 1], k2 = kp[i + 2], k3 = kp[i + 3];
                a0 = fmaf(qv[i+0].x, k0.x, a0); a0 = fmaf(qv[i+0].y, k0.y, a0);
                a0 = fmaf(qv[i+0].z, k0.z, a0); a0 = fmaf(qv[i+0].w, k0.w, a0);
                a1 = fmaf(qv[i+1].x, k1.x, a1); a1 = fmaf(qv[i+1].y, k1.y, a1);
                a1 = fmaf(qv[i+1].z, k1.z, a1); a1 = fmaf(qv[i+1].w, k1.w, a1);
                a2 = fmaf(qv[i+2].x, k2.x, a2); a2 = fmaf(qv[i+2].y, k2.y, a2);
                a2 = fmaf(qv[i+2].z, k2.z, a2); a2 = fmaf(qv[i+2].w, k2.w, a2);
                a3 = fmaf(qv[i+3].x, k3.x, a3); a3 = fmaf(qv[i+3].y, k3.y, a3);
                a3 = fmaf(qv[i+3].z, k3.z, a3); a3 = fmaf(qv[i+3].w, k3.w, a3);
            }
            float acc = (a0 + a1) + (a2 + a3);
            s = fmaf(acc, 0.125f, wsh_s[code]);
            sc_s[hh][j] = s;
        }
        mx = fmaxf(mx, s);
    }
    #pragma unroll
    for (int off = 16; off; off >>= 1)
        mx = fmaxf(mx, __shfl_xor_sync(0xffffffffu, mx, off));
    __syncwarp();

    float sum = 0.f;
    for (int j = lane; j < deg; j += 32) {
        float p = __expf(sc_s[hh][j] - mx);
        sc_s[hh][j] = p;
        sum += p;
    }
    #pragma unroll
    for (int off = 16; off; off >>= 1)
        sum += __shfl_xor_sync(0xffffffffu, sum, off);
    const float inv = 1.f / sum;
    __syncwarp();

    const int dof = hh * HD + lane * 2;
    float o0 = 0.f, o1 = 0.f;
    #pragma unroll 4
    for (int j = 0; j < deg; j++) {
        int   m = nbr_s[j] & 0xFFFFF;
        float p = sc_s[hh][j];
        float2 vv = *(const float2*)(g_v2 + (size_t)m * FDIM + dof);
        o0 = fmaf(p, vv.x, o0);
        o1 = fmaf(p, vv.y, o1);
    }
    __half2 h;
    h.x = __float2half_rn(o0 * inv);
    h.y = __float2half_rn(o1 * inv);
    *(__half2*)(g_abatt + (size_t)n * KP + dof) = h;
}

// ---------------- launch ----------------
extern "C" void kernel_launch(void* const* d_in, const int* in_sizes, int n_in,
                              void* d_out, int out_size) {
    const float* x   = (const float*)d_in[0];
    const int*   ei  = (const int*)d_in[1];
    const int*   et  = (const int*)d_in[2];
    const float* etw = (const float*)d_in[3];
    const float* wo  = (const float*)d_in[16];
    const float* bo  = (const float*)d_in[17];
    float* out = (float*)d_out;

    WP3 wqkv, wiqkv, bqkv, biqkv;
    wqkv.p[0]  = (const float*)d_in[4];
    wqkv.p[1]  = (const float*)d_in[6];
    wqkv.p[2]  = (const float*)d_in[8];
    bqkv.p[0]  = (const float*)d_in[5];
    bqkv.p[1]  = (const float*)d_in[7];
    bqkv.p[2]  = (const float*)d_in[9];
    wiqkv.p[0] = (const float*)d_in[10];
    wiqkv.p[1] = (const float*)d_in[12];
    wiqkv.p[2] = (const float*)d_in[14];
    biqkv.p[0] = (const float*)d_in[11];
    biqkv.p[1] = (const float*)d_in[13];
    biqkv.p[2] = (const float*)d_in[15];

    __half *pab, *pwb;
    cudaGetSymbolAddress((void**)&pab, g_ab);
    cudaGetSymbolAddress((void**)&pwb, g_wb);

    cudaFuncSetAttribute(gemm_fuse_kernel,  cudaFuncAttributeMaxDynamicSharedMemorySize, GEMM_SMEM);
    cudaFuncSetAttribute(gemm_main_kernel,  cudaFuncAttributeMaxDynamicSharedMemorySize, GEMM_SMEM);
    cudaFuncSetAttribute(gemm_final_kernel, cudaFuncAttributeMaxDynamicSharedMemorySize, GEMM_SMEM);

    // sparse mask / adjacency
    zero_cnt_kernel<<<(NN + 255) / 256, 256>>>();
    scatter2_kernel<<<(EE + 255) / 256, 256>>>(ei, et);
    csr2_kernel<<<NN, 256>>>();

    // weight-fusion pipeline (fp16 casts)
    conv_wia_kernel<<<dim3(FDIM * FDIM / 4 / 256, 3), 256>>>(wiqkv);
    conv_wt_kernel<<<dim3(FDIM / 32, FDIM / 32, 3), 256>>>(wqkv);
    gemm_fuse_kernel<<<dim3(FDIM / 128, FDIM / 128, 3), 256, GEMM_SMEM>>>();
    conv_cast_kernel<<<FDIM * FDIM / 4 / 256, 256>>>(wo, pwb + (size_t)3 * WPSZ,
                                                     FDIM * FDIM / 4);
    bias_fuse_kernel<<<dim3(FDIM / 256, 3), 256>>>(wiqkv, bqkv, biqkv);

    // fp16 cast of x
    conv_cast_kernel<<<NN * FDIM / 4 / 256, 256>>>(x, pab, NN * FDIM / 4);

    // q2/k2/v2 in one launch
    gemm_main_kernel<<<dim3(FDIM / 128, NN / 128, 3), 256, GEMM_SMEM>>>();

    attn_sparse_kernel<<<NN, 512>>>(etw);

    gemm_final_kernel<<<dim3(FDIM / 128, NN / 128), 256, GEMM_SMEM>>>(bo, out);
}

// round 11
// speedup vs baseline: 6.0114x; 1.1064x over previous
#include <cuda_runtime.h>
#include <cuda_fp16.h>
#include <math.h>
#include <stdint.h>

#define NN     3072
#define EE     98304
#define FDIM   1024
#define HD     64
#define MAXDEG 256
#define KP     1024          // fp16 GEMM K
#define NTP    (KP / 32)     // 32 BK32 tiles
#define WPSZ   ((size_t)FDIM * KP)

// ---------------- scratch (static device arrays; no allocation) ----------------
__device__ int   g_cnt[NN];                   // zero-init; csr2 resets after use
__device__ int   g_ecol[NN * MAXDEG];
__device__ int   g_eeid[NN * MAXDEG];
__device__ int   g_adj[NN * MAXDEG];
__device__ int   g_deg[NN];
__device__ float g_q2[NN * FDIM];             // fp32 (read once per block)
__device__ __half g_k2h[NN * FDIM];           // fp16 (gathered many times)
__device__ __half g_v2h[NN * FDIM];
__device__ float g_bf[3 * FDIM];              // fused biases
__device__ float g_zb[FDIM];                  // zero bias (static zero-init)
__device__ __half g_ab   [NN * KP];           // fp16 cast of x
__device__ __half g_abatt[NN * KP];           // fp16 cast of attn out
__device__ __half g_wia[3 * WPSZ];            // fp16 cast of Wiq/Wik/Wiv
__device__ __half g_wtb[3 * WPSZ];            // fp16 cast of Wq^T/Wk^T/Wv^T
__device__ __half g_wb [4 * WPSZ];            // fp16: Wf0..2 (from fuse), wo

// ---------------- PTX helpers ----------------
__device__ __forceinline__ uint32_t smem_u32(const void* p) {
    uint32_t a;
    asm("{ .reg .u64 t; cvta.to.shared.u64 t, %1; cvt.u32.u64 %0, t; }" : "=r"(a) : "l"(p));
    return a;
}
__device__ __forceinline__ void cp16(uint32_t dst, const void* src) {
    asm volatile("cp.async.cg.shared.global [%0], [%1], 16;" :: "r"(dst), "l"(src));
}
__device__ __forceinline__ void ldsm4(uint32_t* r, uint32_t a) {
    asm volatile("ldmatrix.sync.aligned.m8n8.x4.shared.b16 {%0,%1,%2,%3}, [%4];"
                 : "=r"(r[0]), "=r"(r[1]), "=r"(r[2]), "=r"(r[3]) : "r"(a));
}
__device__ __forceinline__ void ldsm2(uint32_t* r, uint32_t a) {
    asm volatile("ldmatrix.sync.aligned.m8n8.x2.shared.b16 {%0,%1}, [%2];"
                 : "=r"(r[0]), "=r"(r[1]) : "r"(a));
}
__device__ __forceinline__ void mma16816(float* c, const uint32_t* a, const uint32_t* b) {
    asm volatile(
        "mma.sync.aligned.m16n8k16.row.col.f32.f16.f16.f32 "
        "{%0,%1,%2,%3}, {%4,%5,%6,%7}, {%8,%9}, {%0,%1,%2,%3};"
        : "+f"(c[0]), "+f"(c[1]), "+f"(c[2]), "+f"(c[3])
        : "r"(a[0]), "r"(a[1]), "r"(a[2]), "r"(a[3]), "r"(b[0]), "r"(b[1]));
}

// ---------------- phase 1: all independent prep work in ONE launch ----------------
// blocks [0,3072)      conv_wia  (fp16 cast of Wiq/Wik/Wiv)
// blocks [3072,6144)   conv_wt   (transpose-cast of Wq/Wk/Wv)
// blocks [6144,7168)   wo cast
// blocks [7168,10240)  x cast
// blocks [10240,10624) edge scatter
// blocks [10624,10636) bias fuse
#define P1_BLOCKS 10636

struct ProArgs {
    const float *x;
    const int   *ei, *et;
    const float *wq, *wk, *wv, *wiq, *wik, *wiv, *wo;
    const float *bq, *bk, *bv, *biq, *bik, *biv;
};

__global__ __launch_bounds__(256) void prologue_kernel(ProArgs a) {
    const int b   = blockIdx.x;
    const int tid = threadIdx.x;

    if (b < 3072) {                                   // ---- conv_wia ----
        const int w  = b >> 10;
        const int i  = (b & 1023) * 256 + tid;
        const float* W = (w == 0) ? a.wiq : (w == 1) ? a.wik : a.wiv;
        float4 v = ((const float4*)W)[i];
        __half2 h01, h23;
        h01.x = __float2half_rn(v.x); h01.y = __float2half_rn(v.y);
        h23.x = __float2half_rn(v.z); h23.y = __float2half_rn(v.w);
        __half* A = g_wia + (size_t)w * WPSZ;
        *(__half2*)(A + i * 4)     = h01;
        *(__half2*)(A + i * 4 + 2) = h23;
    } else if (b < 6144) {                            // ---- conv_wt ----
        const int bb = b - 3072;
        const int w  = bb >> 10;
        const int t2 = bb & 1023;
        const int n0 = (t2 & 31) * 32;
        const int k0 = (t2 >> 5) * 32;
        const float* W = (w == 0) ? a.wq : (w == 1) ? a.wk : a.wv;
        __shared__ float t[32][33];
        const int tx = tid & 31;
        const int ty = tid >> 5;
        #pragma unroll
        for (int r = ty; r < 32; r += 8)
            t[r][tx] = W[(size_t)(k0 + r) * FDIM + n0 + tx];
        __syncthreads();
        __half* B = g_wtb + (size_t)w * WPSZ;
        #pragma unroll
        for (int rr = ty; rr < 32; rr += 8)
            B[(size_t)(n0 + rr) * KP + k0 + tx] = __float2half_rn(t[tx][rr]);
    } else if (b < 7168) {                            // ---- wo cast ----
        const int i = (b - 6144) * 256 + tid;
        float4 v = ((const float4*)a.wo)[i];
        __half2 h01, h23;
        h01.x = __float2half_rn(v.x); h01.y = __float2half_rn(v.y);
        h23.x = __float2half_rn(v.z); h23.y = __float2half_rn(v.w);
        __half* A = g_wb + (size_t)3 * WPSZ;
        *(__half2*)(A + i * 4)     = h01;
        *(__half2*)(A + i * 4 + 2) = h23;
    } else if (b < 10240) {                           // ---- x cast ----
        const int i = (b - 7168) * 256 + tid;
        float4 v = ((const float4*)a.x)[i];
        __half2 h01, h23;
        h01.x = __float2half_rn(v.x); h01.y = __float2half_rn(v.y);
        h23.x = __float2half_rn(v.z); h23.y = __float2half_rn(v.w);
        *(__half2*)(g_ab + i * 4)     = h01;
        *(__half2*)(g_ab + i * 4 + 2) = h23;
    } else if (b < 10624) {                           // ---- edge scatter ----
        const int e = (b - 10240) * 256 + tid;
        int s = a.ei[e], d = a.ei[EE + e];
        int pos = atomicAdd(&g_cnt[s], 1);
        if (pos < MAXDEG) {
            g_ecol[s * MAXDEG + pos] = d | (a.et[e] << 20);
            g_eeid[s * MAXDEG + pos] = e;
        }
    } else {                                          // ---- bias fuse ----
        const int idx = b - 10624;
        const int z   = idx >> 2;
        const int n   = (idx & 3) * 256 + tid;
        const float* W  = ((z == 0) ? a.wiq : (z == 1) ? a.wik : a.wiv) + (size_t)n * FDIM;
        const float* bi = (z == 0) ? a.bq : (z == 1) ? a.bk : a.bv;
        const float* bo = (z == 0) ? a.biq : (z == 1) ? a.bik : a.biv;
        float s = 0.f;
        #pragma unroll 8
        for (int k = 0; k < FDIM; k++) s = fmaf(W[k], bi[k], s);
        g_bf[z * FDIM + n] = s + bo[n];
    }
}

// ---------------- mma.sync fp16 GEMM core ----------------
#define STAGE_BYTES 16384
#define GEMM_SMEM   (3 * STAGE_BYTES)

__device__ __forceinline__ void load_tile_pair(
    const __half* Abase, const __half* Bbase,
    int row0, int col0, int k0, uint32_t sA, uint32_t sB, int tid)
{
    #pragma unroll
    for (int i = 0; i < 2; i++) {
        int c   = tid + i * 256;
        int row = c >> 2;
        int kc  = c & 3;
        uint32_t soff = (uint32_t)(((row >> 3) * 4 + kc) * 128 + (row & 7) * 16);
        cp16(sA + soff, Abase + (size_t)(row0 + row) * KP + k0 + kc * 8);
        cp16(sB + soff, Bbase + (size_t)(col0 + row) * KP + k0 + kc * 8);
    }
}

// MODE 0: fp32 out + bias.  MODE 1: fp16 out + bias.  Row stride FDIM both.
template<int MODE>
__device__ __forceinline__ void gemm_core(
    int bx, int by,
    const __half* __restrict__ A, const __half* __restrict__ B,
    const float* __restrict__ bias, float* __restrict__ Yf,
    __half* __restrict__ Ys)
{
    extern __shared__ char smem[];
    const uint32_t sb = smem_u32(smem);
    const int tid  = threadIdx.x;
    const int wid  = tid >> 5;
    const int lane = tid & 31;
    const int wm   = wid & 1;
    const int wn   = wid >> 1;
    const int row0 = by << 7;
    const int col0 = bx << 7;

    const int g  = lane >> 3;
    const int r8 = lane & 7;
    const uint32_t aconst = (uint32_t)((wm * 8 + (g & 1)) * 512 + (g >> 1) * 128 + r8 * 16);
    const uint32_t bconst = (uint32_t)(wn * 4 * 512 + (g & 1) * 128 + r8 * 16);

    float acc[4][4][4];
    #pragma unroll
    for (int mt = 0; mt < 4; mt++)
        #pragma unroll
        for (int nt = 0; nt < 4; nt++)
            acc[mt][nt][0] = acc[mt][nt][1] = acc[mt][nt][2] = acc[mt][nt][3] = 0.f;

    load_tile_pair(A, B, row0, col0, 0, sb, sb + 8192, tid);
    asm volatile("cp.async.commit_group;" ::: "memory");
    load_tile_pair(A, B, row0, col0, 32, sb + STAGE_BYTES, sb + STAGE_BYTES + 8192, tid);
    asm volatile("cp.async.commit_group;" ::: "memory");

    int buf = 0;
    for (int t = 0; t < NTP; t++) {
        asm volatile("cp.async.wait_group 1;" ::: "memory");
        __syncthreads();

        int nbuf = buf + 1; if (nbuf == 3) nbuf = 0;
        int lbuf = nbuf + 1; if (lbuf == 3) lbuf = 0;
        if (t + 2 < NTP) {
            uint32_t ls = sb + (uint32_t)lbuf * STAGE_BYTES;
            load_tile_pair(A, B, row0, col0, (t + 2) * 32, ls, ls + 8192, tid);
        }
        asm volatile("cp.async.commit_group;" ::: "memory");

        const uint32_t Ab = sb + (uint32_t)buf * STAGE_BYTES;
        const uint32_t Bb = Ab + 8192;
        #pragma unroll
        for (int kt = 0; kt < 2; kt++) {
            uint32_t af[4][4], bfr[4][2];
            #pragma unroll
            for (int mt = 0; mt < 4; mt++)
                ldsm4(af[mt], Ab + aconst + (uint32_t)(mt * 1024 + kt * 256));
            #pragma unroll
            for (int nt = 0; nt < 4; nt++)
                ldsm2(bfr[nt], Bb + bconst + (uint32_t)(nt * 512 + kt * 256));
            #pragma unroll
            for (int mt = 0; mt < 4; mt++)
                #pragma unroll
                for (int nt = 0; nt < 4; nt++)
                    mma16816(acc[mt][nt], af[mt], bfr[nt]);
        }
        buf = nbuf;
    }

    const int mbase = row0 + wm * 64 + (lane >> 2);
    const int nbase = col0 + wn * 32 + (lane & 3) * 2;
    #pragma unroll
    for (int mt = 0; mt < 4; mt++) {
        #pragma unroll
        for (int nt = 0; nt < 4; nt++) {
            int m = mbase + mt * 16;
            int n = nbase + nt * 8;
            float2 b2 = *(const float2*)&bias[n];
            float y0 = acc[mt][nt][0] + b2.x, y1 = acc[mt][nt][1] + b2.y;
            float y2 = acc[mt][nt][2] + b2.x, y3 = acc[mt][nt][3] + b2.y;
            if (MODE == 0) {
                *(float2*)&Yf[(size_t)m * FDIM + n]       = make_float2(y0, y1);
                *(float2*)&Yf[(size_t)(m + 8) * FDIM + n] = make_float2(y2, y3);
            } else {
                __half2 h0, h1;
                h0.x = __float2half_rn(y0); h0.y = __float2half_rn(y1);
                h1.x = __float2half_rn(y2); h1.y = __float2half_rn(y3);
                *(__half2*)(Ys + (size_t)m * FDIM + n)       = h0;
                *(__half2*)(Ys + (size_t)(m + 8) * FDIM + n) = h1;
            }
        }
    }
}

// ---------------- phase 2: fuse GEMM (blocks 0..191) + csr dedup (192..3263) ----------------
#define P2_BLOCKS (192 + NN)

__global__ __launch_bounds__(256) void phase2_kernel() {
    if (blockIdx.x < 192) {
        const int b  = blockIdx.x;
        const int z  = b >> 6;
        const int bb = b & 63;
        gemm_core<1>(bb & 7, bb >> 3,
                     g_wia + (size_t)z * WPSZ, g_wtb + (size_t)z * WPSZ,
                     g_zb, nullptr, g_wb + (size_t)z * WPSZ);
        return;
    }
    const int n   = blockIdx.x - 192;
    const int tid = threadIdx.x;
    __shared__ int scol[MAXDEG], seid[MAXDEG];
    __shared__ int outc, sflag;
    if (tid == 0) { outc = 0; sflag = 0; }
    int cnt = g_cnt[n];
    if (cnt > MAXDEG) cnt = MAXDEG;
    if (tid < cnt) {
        scol[tid] = g_ecol[n * MAXDEG + tid];
        seid[tid] = g_eeid[n * MAXDEG + tid];
    }
    __syncthreads();
    if (tid < cnt) {
        int cj = scol[tid] & 0xFFFFF;
        int ej = seid[tid];
        bool win = true;
        for (int i = 0; i < cnt; i++)
            if ((scol[i] & 0xFFFFF) == cj && seid[i] > ej) { win = false; break; }
        if (win) {
            int pos = atomicAdd(&outc, 1);
            g_adj[n * MAXDEG + pos] = scol[tid];
            if (cj == n) sflag = 1;
        }
    }
    __syncthreads();
    if (tid == 0) {
        int d = outc;
        if (!sflag && d < MAXDEG) { g_adj[n * MAXDEG + d] = n | (4 << 20); d++; }
        g_deg[n] = d;
        g_cnt[n] = 0;           // reset for next graph replay (deterministic)
    }
}

// ---------------- phase 3: q2/k2/v2 ----------------
__global__ __launch_bounds__(256) void gemm_main_kernel() {
    const int z = blockIdx.z;
    if (z == 0)
        gemm_core<0>(blockIdx.x, blockIdx.y, g_ab, g_wb, g_bf, g_q2, nullptr);
    else
        gemm_core<1>(blockIdx.x, blockIdx.y, g_ab, g_wb + (size_t)z * WPSZ,
                     g_bf + z * FDIM, nullptr, (z == 1) ? g_k2h : g_v2h);
}

// ---------------- phase 5: out = fl16(att) @ wo + bo ----------------
__global__ __launch_bounds__(256) void gemm_final_kernel(const float* bias, float* Y) {
    gemm_core<0>(blockIdx.x, blockIdx.y, g_abatt, g_wb + (size_t)3 * WPSZ, bias, Y, nullptr);
}

// ---------------- phase 4: sparse gather attention (fp16 K/V) ----------------
__global__ __launch_bounds__(512) void attn_sparse_kernel(const float* __restrict__ etw)
{
    __shared__ float q_s[FDIM];
    __shared__ int   nbr_s[MAXDEG];
    __shared__ float sc_s[16][MAXDEG];
    __shared__ float wsh_s[8];

    const int n    = blockIdx.x;
    const int tid  = threadIdx.x;
    const int hh   = tid >> 5;
    const int lane = tid & 31;

    if (tid < 4) wsh_s[tid + 1] = log1pf(expf(etw[tid]));
    ((float2*)q_s)[tid] = ((const float2*)(g_q2 + (size_t)n * FDIM))[tid];
    const int deg = g_deg[n];
    for (int j = tid; j < deg; j += 512) nbr_s[j] = g_adj[n * MAXDEG + j];
    __syncthreads();

    float4 qv[16];
    #pragma unroll
    for (int i = 0; i < 16; i++) qv[i] = *(const float4*)&q_s[hh * HD + i * 4];

    float mx = -1e30f;
    for (int base = 0; base < deg; base += 32) {
        int   j = base + lane;
        float s = -1e30f;
        if (j < deg) {
            int pk   = nbr_s[j];
            int m    = pk & 0xFFFFF;
            int code = pk >> 20;
            const uint4* kp = (const uint4*)(g_k2h + (size_t)m * FDIM + hh * HD); // 8 x uint4
            float a0 = 0.f, a1 = 0.f;
            #pragma unroll
            for (int i = 0; i < 8; i += 2) {
                uint4 ua = kp[i], ub = kp[i + 1];
                float2 f0 = __half22float2(*(__half2*)&ua.x);
                float2 f1 = __half22float2(*(__half2*)&ua.y);
                float2 f2 = __half22float2(*(__half2*)&ua.z);
                float2 f3 = __half22float2(*(__half2*)&ua.w);
                a0 = fmaf(qv[2*i].x,   f0.x, a0); a0 = fmaf(qv[2*i].y,   f0.y, a0);
                a0 = fmaf(qv[2*i].z,   f1.x, a0); a0 = fmaf(qv[2*i].w,   f1.y, a0);
                a0 = fmaf(qv[2*i+1].x, f2.x, a0); a0 = fmaf(qv[2*i+1].y, f2.y, a0);
                a0 = fmaf(qv[2*i+1].z, f3.x, a0); a0 = fmaf(qv[2*i+1].w, f3.y, a0);
                float2 g0 = __half22float2(*(__half2*)&ub.x);
                float2 g1 = __half22float2(*(__half2*)&ub.y);
                float2 g2 = __half22float2(*(__half2*)&ub.z);
                float2 g3 = __half22float2(*(__half2*)&ub.w);
                a1 = fmaf(qv[2*i+2].x, g0.x, a1); a1 = fmaf(qv[2*i+2].y, g0.y, a1);
                a1 = fmaf(qv[2*i+2].z, g1.x, a1); a1 = fmaf(qv[2*i+2].w, g1.y, a1);
                a1 = fmaf(qv[2*i+3].x, g2.x, a1); a1 = fmaf(qv[2*i+3].y, g2.y, a1);
                a1 = fmaf(qv[2*i+3].z, g3.x, a1); a1 = fmaf(qv[2*i+3].w, g3.y, a1);
            }
            s = fmaf(a0 + a1, 0.125f, wsh_s[code]);
            sc_s[hh][j] = s;
        }
        mx = fmaxf(mx, s);
    }
    #pragma unroll
    for (int off = 16; off; off >>= 1)
        mx = fmaxf(mx, __shfl_xor_sync(0xffffffffu, mx, off));
    __syncwarp();

    float sum = 0.f;
    for (int j = lane; j < deg; j += 32) {
        float p = __expf(sc_s[hh][j] - mx);
        sc_s[hh][j] = p;
        sum += p;
    }
    #pragma unroll
    for (int off = 16; off; off >>= 1)
        sum += __shfl_xor_sync(0xffffffffu, sum, off);
    const float inv = 1.f / sum;
    __syncwarp();

    const int dof = hh * HD + lane * 2;
    float o0 = 0.f, o1 = 0.f;
    #pragma unroll 4
    for (int j = 0; j < deg; j++) {
        int   m = nbr_s[j] & 0xFFFFF;
        float p = sc_s[hh][j];
        float2 f = __half22float2(*(const __half2*)(g_v2h + (size_t)m * FDIM + dof));
        o0 = fmaf(p, f.x, o0);
        o1 = fmaf(p, f.y, o1);
    }
    __half2 h;
    h.x = __float2half_rn(o0 * inv);
    h.y = __float2half_rn(o1 * inv);
    *(__half2*)(g_abatt + (size_t)n * KP + dof) = h;
}

// ---------------- launch ----------------
extern "C" void kernel_launch(void* const* d_in, const int* in_sizes, int n_in,
                              void* d_out, int out_size) {
    ProArgs a;
    a.x   = (const float*)d_in[0];
    a.ei  = (const int*)d_in[1];
    a.et  = (const int*)d_in[2];
    const float* etw = (const float*)d_in[3];
    a.wq  = (const float*)d_in[4];   a.bq  = (const float*)d_in[5];
    a.wk  = (const float*)d_in[6];   a.bk  = (const float*)d_in[7];
    a.wv  = (const float*)d_in[8];   a.bv  = (const float*)d_in[9];
    a.wiq = (const float*)d_in[10];  a.biq = (const float*)d_in[11];
    a.wik = (const float*)d_in[12];  a.bik = (const float*)d_in[13];
    a.wiv = (const float*)d_in[14];  a.biv = (const float*)d_in[15];
    a.wo  = (const float*)d_in[16];
    const float* bo = (const float*)d_in[17];
    float* out = (float*)d_out;

    cudaFuncSetAttribute(phase2_kernel,     cudaFuncAttributeMaxDynamicSharedMemorySize, GEMM_SMEM);
    cudaFuncSetAttribute(gemm_main_kernel,  cudaFuncAttributeMaxDynamicSharedMemorySize, GEMM_SMEM);
    cudaFuncSetAttribute(gemm_final_kernel, cudaFuncAttributeMaxDynamicSharedMemorySize, GEMM_SMEM);

    prologue_kernel<<<P1_BLOCKS, 256>>>(a);
    phase2_kernel<<<P2_BLOCKS, 256, GEMM_SMEM>>>();
    gemm_main_kernel<<<dim3(FDIM / 128, NN / 128, 3), 256, GEMM_SMEM>>>();
    attn_sparse_kernel<<<NN, 512>>>(etw);
    gemm_final_kernel<<<dim3(FDIM / 128, NN / 128), 256, GEMM_SMEM>>>(bo, out);
}